// round 4
// baseline (speedup 1.0000x reference)
#include <cuda_runtime.h>
#include <math.h>

#define NHALF 8192
#define NTOT  16384
#define DDIM  256
#define LDSM  132   // padded smem leading dim (conflict-free, keeps 16B alignment)

// ---- scratch (static device arrays: allowed; no cudaMalloc) ----
__device__ float g_a[(size_t)NTOT * DDIM];   // elu(z @ W1^T + b1)
__device__ float g_n[(size_t)NTOT * DDIM];   // normalized projections [n1; n2]
__device__ float g_rs_same[NTOT];            // sum_j exp(s)/ j in SAME half as i
__device__ float g_rs_cross[NTOT];           // sum_j exp(s)/ j in OTHER half
__device__ float g_diag[NTOT];               // exp(n_i . n_i / tau)
__device__ float g_d12[NHALF];               // exp(n1_i . n2_i / tau)

__global__ void zero_kernel() {
    int i = blockIdx.x * blockDim.x + threadIdx.x;
    if (i < NTOT) { g_rs_same[i] = 0.f; g_rs_cross[i] = 0.f; }
}

// ---------------------------------------------------------------------------
// Projection GEMM: C = act(A @ B^T + bias). 128x128 tile, 8x8 per thread.
// MODE 0: A rows come from z1/z2 (stacked), ELU activation, writes g_a.
// MODE 1: A = g_a, no activation, writes g_n (pre-normalization).
// ---------------------------------------------------------------------------
template <int MODE>
__global__ void __launch_bounds__(256)
proj_kernel(const float* __restrict__ A0, const float* __restrict__ A1,
            const float* __restrict__ B,  const float* __restrict__ bias)
{
    __shared__ __align__(16) float sm[2 * 8 * LDSM];
    float* sA = sm;
    float* sB = sm + 8 * LDSM;

    const int tid = threadIdx.x;
    const int tx = tid & 15, ty = tid >> 4;
    const int row0 = blockIdx.y * 128;
    const int col0 = blockIdx.x * 128;

    float acc[8][8];
#pragma unroll
    for (int i = 0; i < 8; i++)
#pragma unroll
        for (int j = 0; j < 8; j++) acc[i][j] = 0.f;

    const int lr = tid >> 1;          // 0..127
    const int lk = (tid & 1) * 4;     // 0 or 4

    const int arow = row0 + lr;
    const float* aptr;
    if (MODE == 0)
        aptr = (arow < NHALF) ? (A0 + (size_t)arow * DDIM)
                              : (A1 + (size_t)(arow - NHALF) * DDIM);
    else
        aptr = g_a + (size_t)arow * DDIM;
    const float* bptr = B + (size_t)(col0 + lr) * DDIM;

    for (int k0 = 0; k0 < DDIM; k0 += 8) {
        float4 va = *(const float4*)(aptr + k0 + lk);
        float4 vb = *(const float4*)(bptr + k0 + lk);
        sA[(lk + 0) * LDSM + lr] = va.x;
        sA[(lk + 1) * LDSM + lr] = va.y;
        sA[(lk + 2) * LDSM + lr] = va.z;
        sA[(lk + 3) * LDSM + lr] = va.w;
        sB[(lk + 0) * LDSM + lr] = vb.x;
        sB[(lk + 1) * LDSM + lr] = vb.y;
        sB[(lk + 2) * LDSM + lr] = vb.z;
        sB[(lk + 3) * LDSM + lr] = vb.w;
        __syncthreads();
#pragma unroll
        for (int kk = 0; kk < 8; kk++) {
            float a[8], b[8];
            *(float4*)(a)     = *(const float4*)&sA[kk * LDSM + ty * 8];
            *(float4*)(a + 4) = *(const float4*)&sA[kk * LDSM + ty * 8 + 4];
            *(float4*)(b)     = *(const float4*)&sB[kk * LDSM + tx * 8];
            *(float4*)(b + 4) = *(const float4*)&sB[kk * LDSM + tx * 8 + 4];
#pragma unroll
            for (int i = 0; i < 8; i++)
#pragma unroll
                for (int j = 0; j < 8; j++) acc[i][j] += a[i] * b[j];
        }
        __syncthreads();
    }

    float* C = (MODE == 0) ? g_a : g_n;
#pragma unroll
    for (int i = 0; i < 8; i++) {
        int gr = row0 + ty * 8 + i;
#pragma unroll
        for (int j = 0; j < 8; j++) {
            int gc = col0 + tx * 8 + j;
            float v = acc[i][j] + bias[gc];
            if (MODE == 0) v = v > 0.f ? v : expm1f(v);
            C[(size_t)gr * DDIM + gc] = v;
        }
    }
}

// ---------------------------------------------------------------------------
// Row L2-normalize g_n in place. One block per row.
// ---------------------------------------------------------------------------
__global__ void norm_kernel() {
    int row = blockIdx.x;
    int t = threadIdx.x;
    float x = g_n[(size_t)row * DDIM + t];
    float ss = x * x;
#pragma unroll
    for (int o = 16; o; o >>= 1) ss += __shfl_xor_sync(0xffffffffu, ss, o);
    __shared__ float ws[8];
    if ((t & 31) == 0) ws[t >> 5] = ss;
    __syncthreads();
    if (t < 32) {
        float v = (t < 8) ? ws[t] : 0.f;
#pragma unroll
        for (int o = 4; o; o >>= 1) v += __shfl_xor_sync(0xffffffffu, v, o);
        if (t == 0) ws[0] = v;
    }
    __syncthreads();
    float inv = 1.f / fmaxf(sqrtf(ws[0]), 1e-12f);
    g_n[(size_t)row * DDIM + t] = x * inv;
}

// ---------------------------------------------------------------------------
// Fused Gram + exp + reductions. G = M M^T, M = g_n (16384 x 256).
// Upper-triangle tiles only (bj >= bi): each tile contributes
//  - row sums for rows gi (cols in bj range)
//  - col sums (= mirror row sums for rows gj) when bi != bj
// Split destination by same-half vs cross-half. Captures diag and d12.
// ---------------------------------------------------------------------------
__global__ void __launch_bounds__(256)
sim_kernel()
{
    const int bi = blockIdx.y, bj = blockIdx.x;
    if (bj < bi) return;  // symmetry: skip lower triangle

    __shared__ __align__(16) float sm[2 * 8 * LDSM];
    float* sA = sm;
    float* sB = sm + 8 * LDSM;

    const int tid = threadIdx.x;
    const int tx = tid & 15, ty = tid >> 4;
    const int row0 = bi * 128;
    const int col0 = bj * 128;

    float acc[8][8];
#pragma unroll
    for (int i = 0; i < 8; i++)
#pragma unroll
        for (int j = 0; j < 8; j++) acc[i][j] = 0.f;

    const int lr = tid >> 1;
    const int lk = (tid & 1) * 4;
    const float* aptr = g_n + (size_t)(row0 + lr) * DDIM;
    const float* bptr = g_n + (size_t)(col0 + lr) * DDIM;

    for (int k0 = 0; k0 < DDIM; k0 += 8) {
        float4 va = *(const float4*)(aptr + k0 + lk);
        float4 vb = *(const float4*)(bptr + k0 + lk);
        sA[(lk + 0) * LDSM + lr] = va.x;
        sA[(lk + 1) * LDSM + lr] = va.y;
        sA[(lk + 2) * LDSM + lr] = va.z;
        sA[(lk + 3) * LDSM + lr] = va.w;
        sB[(lk + 0) * LDSM + lr] = vb.x;
        sB[(lk + 1) * LDSM + lr] = vb.y;
        sB[(lk + 2) * LDSM + lr] = vb.z;
        sB[(lk + 3) * LDSM + lr] = vb.w;
        __syncthreads();
#pragma unroll
        for (int kk = 0; kk < 8; kk++) {
            float a[8], b[8];
            *(float4*)(a)     = *(const float4*)&sA[kk * LDSM + ty * 8];
            *(float4*)(a + 4) = *(const float4*)&sA[kk * LDSM + ty * 8 + 4];
            *(float4*)(b)     = *(const float4*)&sB[kk * LDSM + tx * 8];
            *(float4*)(b + 4) = *(const float4*)&sB[kk * LDSM + tx * 8 + 4];
#pragma unroll
            for (int i = 0; i < 8; i++)
#pragma unroll
                for (int j = 0; j < 8; j++) acc[i][j] += a[i] * b[j];
        }
        __syncthreads();
    }

    const bool same = ((bi < 64) == (bj < 64));
    float* rs = same ? g_rs_same : g_rs_cross;

    float cs[8];
#pragma unroll
    for (int j = 0; j < 8; j++) cs[j] = 0.f;

#pragma unroll
    for (int i = 0; i < 8; i++) {
        const int gi = row0 + ty * 8 + i;
        float rp = 0.f;
#pragma unroll
        for (int j = 0; j < 8; j++) {
            const int gc = col0 + tx * 8 + j;
            float e = __expf(acc[i][j] * 2.0f);  // 1/TAU = 2
            rp += e;
            cs[j] += e;
            if (gc == gi) g_diag[gi] = e;            // only on diagonal tiles
            if (gc == gi + NHALF) g_d12[gi] = e;     // only on bj == bi+64 tiles
        }
        // reduce row partial across the 16 tx lanes (lane = (ty&1)*16 + tx)
#pragma unroll
        for (int o = 8; o; o >>= 1) rp += __shfl_xor_sync(0xffffffffu, rp, o);
        if (tx == 0) atomicAdd(&rs[gi], rp);
    }

    if (bi != bj) {
        // column sums -> mirror rows gj (same/cross flag is symmetric)
        float* red = sm;  // 2048 floats needed, 2112 available; K-loop done
#pragma unroll
        for (int j = 0; j < 8; j++) red[ty * 128 + tx * 8 + j] = cs[j];
        __syncthreads();
        if (tid < 128) {
            float s = 0.f;
#pragma unroll
            for (int yy = 0; yy < 16; yy++) s += red[yy * 128 + tid];
            atomicAdd(&rs[col0 + tid], s);
        }
    }
}

__global__ void finalize_kernel(float* __restrict__ out) {
    int i = blockIdx.x * blockDim.x + threadIdx.x;
    if (i >= NHALF) return;
    float d12  = g_d12[i];
    float den1 = g_rs_same[i] + g_rs_cross[i] - g_diag[i];
    float den2 = g_rs_same[i + NHALF] + g_rs_cross[i + NHALF] - g_diag[i + NHALF];
    float ld = logf(d12);
    out[i] = 0.5f * ((logf(den1) - ld) + (logf(den2) - ld));
}

extern "C" void kernel_launch(void* const* d_in, const int* in_sizes, int n_in,
                              void* d_out, int out_size) {
    const float* z1 = (const float*)d_in[0];
    const float* z2 = (const float*)d_in[1];
    const float* W1 = (const float*)d_in[2];
    const float* b1 = (const float*)d_in[3];
    const float* W2 = (const float*)d_in[4];
    const float* b2 = (const float*)d_in[5];
    float* out = (float*)d_out;

    zero_kernel<<<(NTOT + 255) / 256, 256>>>();
    // h = elu(z @ W1^T + b1): 16384 x 256, tiles (cols=2, rows=128)
    proj_kernel<0><<<dim3(2, 128), 256>>>(z1, z2, W1, b1);
    // n = a @ W2^T + b2
    proj_kernel<1><<<dim3(2, 128), 256>>>(nullptr, nullptr, W2, b2);
    norm_kernel<<<NTOT, 256>>>();
    sim_kernel<<<dim3(128, 128), 256>>>();
    finalize_kernel<<<NHALF / 256, 256>>>(out);
}

// round 7
// speedup vs baseline: 3.2890x; 3.2890x over previous
#include <cuda_runtime.h>
#include <cuda_bf16.h>
#include <math.h>
#include <stdint.h>

#define NHALF 8192
#define NTOT  16384
#define DDIM  256
#define LDSM_F  132
#define STRB  528            // bf16 tile row stride in bytes (512 + 16 pad)
#define TILE_BYTES (128 * STRB)
#define SIM_SMEM (2 * TILE_BYTES)
#define NTILE_LIN 8256       // 129*128/2 upper-triangle tiles

// ---- scratch ----
__device__ float g_a[(size_t)NTOT * DDIM];
__device__ float g_n[(size_t)NTOT * DDIM];
__device__ __nv_bfloat16 g_nb[(size_t)NTOT * DDIM];
__device__ float g_rs_same[NTOT];
__device__ float g_rs_cross[NTOT];
__device__ float g_s12[NHALF];   // exact fp32 dot(n1_i, n2_i)

static __device__ __forceinline__ uint32_t smem_u32(const void* p) {
    uint32_t a;
    asm("{ .reg .u64 t; cvta.to.shared.u64 t, %1; cvt.u32.u64 %0, t; }"
        : "=r"(a) : "l"(p));
    return a;
}

static __device__ __forceinline__ void ldsm4(uint32_t& r0, uint32_t& r1,
                                             uint32_t& r2, uint32_t& r3,
                                             uint32_t addr) {
    asm volatile("ldmatrix.sync.aligned.m8n8.x4.shared.b16 {%0,%1,%2,%3}, [%4];"
                 : "=r"(r0), "=r"(r1), "=r"(r2), "=r"(r3) : "r"(addr));
}

static __device__ __forceinline__ void mma16816(float* d, const uint32_t* a,
                                                uint32_t b0, uint32_t b1) {
    asm volatile(
        "mma.sync.aligned.m16n8k16.row.col.f32.bf16.bf16.f32 "
        "{%0,%1,%2,%3}, {%4,%5,%6,%7}, {%8,%9}, {%0,%1,%2,%3};"
        : "+f"(d[0]), "+f"(d[1]), "+f"(d[2]), "+f"(d[3])
        : "r"(a[0]), "r"(a[1]), "r"(a[2]), "r"(a[3]), "r"(b0), "r"(b1));
}

__global__ void zero_kernel() {
    int i = blockIdx.x * blockDim.x + threadIdx.x;
    if (i < NTOT) { g_rs_same[i] = 0.f; g_rs_cross[i] = 0.f; }
}

// ---------------------------------------------------------------------------
// Projection GEMM (fp32 SIMT — keeps accuracy anchor; ~10% of runtime)
// ---------------------------------------------------------------------------
template <int MODE>
__global__ void __launch_bounds__(256)
proj_kernel(const float* __restrict__ A0, const float* __restrict__ A1,
            const float* __restrict__ B,  const float* __restrict__ bias)
{
    __shared__ __align__(16) float sm[2 * 8 * LDSM_F];
    float* sA = sm;
    float* sB = sm + 8 * LDSM_F;

    const int tid = threadIdx.x;
    const int tx = tid & 15, ty = tid >> 4;
    const int row0 = blockIdx.y * 128;
    const int col0 = blockIdx.x * 128;

    float acc[8][8];
#pragma unroll
    for (int i = 0; i < 8; i++)
#pragma unroll
        for (int j = 0; j < 8; j++) acc[i][j] = 0.f;

    const int lr = tid >> 1;
    const int lk = (tid & 1) * 4;

    const int arow = row0 + lr;
    const float* aptr;
    if (MODE == 0)
        aptr = (arow < NHALF) ? (A0 + (size_t)arow * DDIM)
                              : (A1 + (size_t)(arow - NHALF) * DDIM);
    else
        aptr = g_a + (size_t)arow * DDIM;
    const float* bptr = B + (size_t)(col0 + lr) * DDIM;

    for (int k0 = 0; k0 < DDIM; k0 += 8) {
        float4 va = *(const float4*)(aptr + k0 + lk);
        float4 vb = *(const float4*)(bptr + k0 + lk);
        sA[(lk + 0) * LDSM_F + lr] = va.x;
        sA[(lk + 1) * LDSM_F + lr] = va.y;
        sA[(lk + 2) * LDSM_F + lr] = va.z;
        sA[(lk + 3) * LDSM_F + lr] = va.w;
        sB[(lk + 0) * LDSM_F + lr] = vb.x;
        sB[(lk + 1) * LDSM_F + lr] = vb.y;
        sB[(lk + 2) * LDSM_F + lr] = vb.z;
        sB[(lk + 3) * LDSM_F + lr] = vb.w;
        __syncthreads();
#pragma unroll
        for (int kk = 0; kk < 8; kk++) {
            float a[8], b[8];
            *(float4*)(a)     = *(const float4*)&sA[kk * LDSM_F + ty * 8];
            *(float4*)(a + 4) = *(const float4*)&sA[kk * LDSM_F + ty * 8 + 4];
            *(float4*)(b)     = *(const float4*)&sB[kk * LDSM_F + tx * 8];
            *(float4*)(b + 4) = *(const float4*)&sB[kk * LDSM_F + tx * 8 + 4];
#pragma unroll
            for (int i = 0; i < 8; i++)
#pragma unroll
                for (int j = 0; j < 8; j++) acc[i][j] += a[i] * b[j];
        }
        __syncthreads();
    }

    float* C = (MODE == 0) ? g_a : g_n;
#pragma unroll
    for (int i = 0; i < 8; i++) {
        int gr = row0 + ty * 8 + i;
#pragma unroll
        for (int j = 0; j < 8; j++) {
            int gc = col0 + tx * 8 + j;
            float v = acc[i][j] + bias[gc];
            if (MODE == 0) v = v > 0.f ? v : expm1f(v);
            C[(size_t)gr * DDIM + gc] = v;
        }
    }
}

// ---------------------------------------------------------------------------
// Row L2-normalize (in place) + emit bf16 copy.
// ---------------------------------------------------------------------------
__global__ void norm_kernel() {
    int row = blockIdx.x;
    int t = threadIdx.x;
    float x = g_n[(size_t)row * DDIM + t];
    float ss = x * x;
#pragma unroll
    for (int o = 16; o; o >>= 1) ss += __shfl_xor_sync(0xffffffffu, ss, o);
    __shared__ float ws[8];
    if ((t & 31) == 0) ws[t >> 5] = ss;
    __syncthreads();
    if (t < 32) {
        float v = (t < 8) ? ws[t] : 0.f;
#pragma unroll
        for (int o = 4; o; o >>= 1) v += __shfl_xor_sync(0xffffffffu, v, o);
        if (t == 0) ws[0] = v;
    }
    __syncthreads();
    float inv = 1.f / fmaxf(sqrtf(ws[0]), 1e-12f);
    float nv = x * inv;
    g_n[(size_t)row * DDIM + t] = nv;
    g_nb[(size_t)row * DDIM + t] = __float2bfloat16(nv);
}

// Exact fp32 s12_i = dot(n1_i, n2_i)
__global__ void d12_kernel() {
    int i = blockIdx.x;
    int t = threadIdx.x;
    float p = g_n[(size_t)i * DDIM + t] * g_n[(size_t)(i + NHALF) * DDIM + t];
#pragma unroll
    for (int o = 16; o; o >>= 1) p += __shfl_xor_sync(0xffffffffu, p, o);
    __shared__ float ws[8];
    if ((t & 31) == 0) ws[t >> 5] = p;
    __syncthreads();
    if (t == 0) {
        float s = 0.f;
#pragma unroll
        for (int w = 0; w < 8; w++) s += ws[w];
        g_s12[i] = s;
    }
}

// ---------------------------------------------------------------------------
// Gram + exp + reductions via mma.sync bf16 (HMMA — compute_103-legal).
// 128x128x256 tile per CTA; 8 warps as 4(row) x 2(col); warp tile 32x64.
// Linearized upper-triangle grid. Column sums mirror to rows of bj.
// ---------------------------------------------------------------------------
__global__ void __launch_bounds__(256, 1)
sim_mma()
{
    extern __shared__ char smem[];

    // Triangular decode: bi = largest b with b*(257-b)/2 <= t
    const int t = blockIdx.x;
    int bi = (int)((257.0 - sqrt(66049.0 - 8.0 * (double)t)) * 0.5);
    if (bi < 0) bi = 0;
    if (bi > 127) bi = 127;
    while (bi > 0 && bi * (257 - bi) / 2 > t) bi--;
    while (bi < 127 && (bi + 1) * (257 - (bi + 1)) / 2 <= t) bi++;
    const int bj = bi + (t - bi * (257 - bi) / 2);

    const int tid = threadIdx.x;
    const int wid = tid >> 5, lane = tid & 31;
    const int wr = wid & 3;        // warp row: 32 rows each
    const int wc = wid >> 2;       // warp col: 64 cols each
    const int row0 = bi * 128, col0 = bj * 128;

    const uint32_t sA = smem_u32(smem);
    const uint32_t sB = (bi == bj) ? sA : (sA + TILE_BYTES);

    // ---- load tiles (row-major bf16, 512B/row -> 528B-stride smem) ----
    {
        const char* srcA = (const char*)g_nb + (size_t)row0 * 512;
        char* dstA = smem;
#pragma unroll 4
        for (int it = 0; it < 16; it++) {
            int u = tid + it * 256;          // 16B units, 0..4095
            int r = u >> 5;
            int c = u & 31;
            *(uint4*)(dstA + r * STRB + c * 16) =
                *(const uint4*)(srcA + (size_t)r * 512 + c * 16);
        }
        if (bj != bi) {
            const char* srcB = (const char*)g_nb + (size_t)col0 * 512;
            char* dstB = smem + TILE_BYTES;
#pragma unroll 4
            for (int it = 0; it < 16; it++) {
                int u = tid + it * 256;
                int r = u >> 5;
                int c = u & 31;
                *(uint4*)(dstB + r * STRB + c * 16) =
                    *(const uint4*)(srcB + (size_t)r * 512 + c * 16);
            }
        }
    }
    __syncthreads();

    // ---- MMA mainloop ----
    float d[2][8][4];
#pragma unroll
    for (int mi = 0; mi < 2; mi++)
#pragma unroll
        for (int ni = 0; ni < 8; ni++)
#pragma unroll
            for (int q = 0; q < 4; q++) d[mi][ni][q] = 0.f;

    const int lrow = lane & 15;          // ldmatrix row provider
    const int lkof = (lane >> 4) * 16;   // +8 bf16 elems for upper 16 lanes

    for (int ks = 0; ks < 16; ks++) {
        const int kb = ks * 32;          // k byte offset (16 bf16 = 32B)
        uint32_t a[2][4];
#pragma unroll
        for (int mi = 0; mi < 2; mi++) {
            uint32_t addr = sA + (wr * 32 + mi * 16 + lrow) * STRB + kb + lkof;
            ldsm4(a[mi][0], a[mi][1], a[mi][2], a[mi][3], addr);
        }
        uint32_t b0[8], b1[8];
#pragma unroll
        for (int nq = 0; nq < 4; nq++) {
            uint32_t addr = sB + (wc * 64 + nq * 16 + lrow) * STRB + kb + lkof;
            uint32_t q0, q1, q2, q3;
            ldsm4(q0, q1, q2, q3, addr);
            b0[nq * 2] = q0;     b1[nq * 2] = q2;      // n-group nq*2
            b0[nq * 2 + 1] = q1; b1[nq * 2 + 1] = q3;  // n-group nq*2+1
        }
#pragma unroll
        for (int mi = 0; mi < 2; mi++)
#pragma unroll
            for (int ni = 0; ni < 8; ni++)
                mma16816(d[mi][ni], a[mi], b0[ni], b1[ni]);
    }

    // ---- epilogue: exp, row sums, col sums ----
    const bool same = ((bi < 64) == (bj < 64));
    float* rs = same ? g_rs_same : g_rs_cross;

    float cp0[8], cp1[8];
#pragma unroll
    for (int ni = 0; ni < 8; ni++) { cp0[ni] = 0.f; cp1[ni] = 0.f; }

#pragma unroll
    for (int mi = 0; mi < 2; mi++) {
        float rp0 = 0.f, rp1 = 0.f;
#pragma unroll
        for (int ni = 0; ni < 8; ni++) {
            float e0 = __expf(2.f * d[mi][ni][0]);
            float e1 = __expf(2.f * d[mi][ni][1]);
            float e2 = __expf(2.f * d[mi][ni][2]);
            float e3 = __expf(2.f * d[mi][ni][3]);
            rp0 += e0 + e1;  rp1 += e2 + e3;        // rows lane/4, lane/4+8
            cp0[ni] += e0 + e2;  cp1[ni] += e1 + e3; // cols (lane%4)*2, +1
        }
        rp0 += __shfl_xor_sync(0xffffffffu, rp0, 1);
        rp0 += __shfl_xor_sync(0xffffffffu, rp0, 2);
        rp1 += __shfl_xor_sync(0xffffffffu, rp1, 1);
        rp1 += __shfl_xor_sync(0xffffffffu, rp1, 2);
        if ((lane & 3) == 0) {
            int br = row0 + wr * 32 + mi * 16 + (lane >> 2);
            atomicAdd(&rs[br], rp0);
            atomicAdd(&rs[br + 8], rp1);
        }
    }

    if (bi != bj) {
#pragma unroll
        for (int ni = 0; ni < 8; ni++) {
            cp0[ni] += __shfl_xor_sync(0xffffffffu, cp0[ni], 4);
            cp0[ni] += __shfl_xor_sync(0xffffffffu, cp0[ni], 8);
            cp0[ni] += __shfl_xor_sync(0xffffffffu, cp0[ni], 16);
            cp1[ni] += __shfl_xor_sync(0xffffffffu, cp1[ni], 4);
            cp1[ni] += __shfl_xor_sync(0xffffffffu, cp1[ni], 8);
            cp1[ni] += __shfl_xor_sync(0xffffffffu, cp1[ni], 16);
        }
        if (lane < 4) {
#pragma unroll
            for (int ni = 0; ni < 8; ni++) {
                int bc = col0 + wc * 64 + ni * 8 + lane * 2;
                atomicAdd(&rs[bc], cp0[ni]);
                atomicAdd(&rs[bc + 1], cp1[ni]);
            }
        }
    }
}

__global__ void finalize_kernel(float* __restrict__ out) {
    int i = blockIdx.x * blockDim.x + threadIdx.x;
    if (i >= NHALF) return;
    const float E2 = 7.389056098930650f;   // exp(2) diagonal term (||n||=1)
    float den1 = g_rs_same[i] + g_rs_cross[i] - E2;
    float den2 = g_rs_same[i + NHALF] + g_rs_cross[i + NHALF] - E2;
    float twos = 2.0f * g_s12[i];
    out[i] = 0.5f * ((logf(den1) - twos) + (logf(den2) - twos));
}

extern "C" void kernel_launch(void* const* d_in, const int* in_sizes, int n_in,
                              void* d_out, int out_size) {
    const float* z1 = (const float*)d_in[0];
    const float* z2 = (const float*)d_in[1];
    const float* W1 = (const float*)d_in[2];
    const float* b1 = (const float*)d_in[3];
    const float* W2 = (const float*)d_in[4];
    const float* b2 = (const float*)d_in[5];
    float* out = (float*)d_out;

    cudaFuncSetAttribute(sim_mma, cudaFuncAttributeMaxDynamicSharedMemorySize,
                         SIM_SMEM);

    zero_kernel<<<(NTOT + 255) / 256, 256>>>();
    proj_kernel<0><<<dim3(2, 128), 256>>>(z1, z2, W1, b1);
    proj_kernel<1><<<dim3(2, 128), 256>>>(nullptr, nullptr, W2, b2);
    norm_kernel<<<NTOT, 256>>>();
    d12_kernel<<<NHALF, 256>>>();
    sim_mma<<<NTILE_LIN, 256, SIM_SMEM>>>();
    finalize_kernel<<<NHALF / 256, 256>>>(out);
}

// round 8
// speedup vs baseline: 4.3170x; 1.3126x over previous
#include <cuda_runtime.h>
#include <cuda_bf16.h>
#include <math.h>
#include <stdint.h>

#define NHALF 8192
#define NTOT  16384
#define DDIM  256
#define STRB  528            // sim: bf16 tile row stride in bytes (512 + 16 pad)
#define TILE_BYTES (128 * STRB)
#define SIM_SMEM (2 * TILE_BYTES)
#define NTILE_LIN 8256       // 129*128/2 upper-triangle tiles
#define PSTR  68             // proj: tf32 smem row stride in 4B words (64 + 4)
#define PROJ_SMEM (2 * 128 * PSTR * 4)

// ---- scratch ----
__device__ float g_a[(size_t)NTOT * DDIM];
__device__ float g_n[(size_t)NTOT * DDIM];
__device__ __nv_bfloat16 g_nb[(size_t)NTOT * DDIM];
__device__ float g_rs_same[NTOT];
__device__ float g_rs_cross[NTOT];
__device__ float g_s12[NHALF];

static __device__ __forceinline__ uint32_t smem_u32(const void* p) {
    uint32_t a;
    asm("{ .reg .u64 t; cvta.to.shared.u64 t, %1; cvt.u32.u64 %0, t; }"
        : "=r"(a) : "l"(p));
    return a;
}

static __device__ __forceinline__ void ldsm4(uint32_t& r0, uint32_t& r1,
                                             uint32_t& r2, uint32_t& r3,
                                             uint32_t addr) {
    asm volatile("ldmatrix.sync.aligned.m8n8.x4.shared.b16 {%0,%1,%2,%3}, [%4];"
                 : "=r"(r0), "=r"(r1), "=r"(r2), "=r"(r3) : "r"(addr));
}

static __device__ __forceinline__ void mma16816(float* d, const uint32_t* a,
                                                uint32_t b0, uint32_t b1) {
    asm volatile(
        "mma.sync.aligned.m16n8k16.row.col.f32.bf16.bf16.f32 "
        "{%0,%1,%2,%3}, {%4,%5,%6,%7}, {%8,%9}, {%0,%1,%2,%3};"
        : "+f"(d[0]), "+f"(d[1]), "+f"(d[2]), "+f"(d[3])
        : "r"(a[0]), "r"(a[1]), "r"(a[2]), "r"(a[3]), "r"(b0), "r"(b1));
}

static __device__ __forceinline__ void mma_tf32(float* d, const uint32_t* a,
                                                uint32_t b0, uint32_t b1) {
    asm volatile(
        "mma.sync.aligned.m16n8k8.row.col.f32.tf32.tf32.f32 "
        "{%0,%1,%2,%3}, {%4,%5,%6,%7}, {%8,%9}, {%0,%1,%2,%3};"
        : "+f"(d[0]), "+f"(d[1]), "+f"(d[2]), "+f"(d[3])
        : "r"(a[0]), "r"(a[1]), "r"(a[2]), "r"(a[3]), "r"(b0), "r"(b1));
}

static __device__ __forceinline__ uint32_t f2tf32(float x) {
    uint32_t u;
    asm("cvt.rna.tf32.f32 %0, %1;" : "=r"(u) : "f"(x));
    return u;
}

#define CP_ASYNC16(dst, src) \
    asm volatile("cp.async.cg.shared.global [%0], [%1], 16;" \
                 :: "r"(dst), "l"(src) : "memory")
#define CP_COMMIT() asm volatile("cp.async.commit_group;" ::: "memory")
#define CP_WAIT(n)  asm volatile("cp.async.wait_group %0;" :: "n"(n) : "memory")

__global__ void zero_kernel() {
    int i = blockIdx.x * blockDim.x + threadIdx.x;
    if (i < NTOT) { g_rs_same[i] = 0.f; g_rs_cross[i] = 0.f; }
}

// ---------------------------------------------------------------------------
// Projection GEMM via tf32 mma.sync. C = act(A @ B^T + bias).
// CTA: 128 rows x 128 cols, K=256 in 4 chunks of 64.
// 8 warps = 4(row:32) x 2(col:64). Warp: 2x8 m16n8k8 frags, 8 ksteps/chunk.
// MODE 0: A from z1/z2 stacked, ELU, -> g_a.  MODE 1: A = g_a -> g_n.
// ---------------------------------------------------------------------------
template <int MODE>
__global__ void __launch_bounds__(256, 1)
proj_tc(const float* __restrict__ A0, const float* __restrict__ A1,
        const float* __restrict__ B,  const float* __restrict__ bias)
{
    extern __shared__ uint32_t psm[];
    uint32_t* sA = psm;                 // [128][PSTR] tf32 bits
    uint32_t* sB = psm + 128 * PSTR;

    const int tid = threadIdx.x;
    const int wid = tid >> 5, lane = tid & 31;
    const int wr = wid & 3, wc = wid >> 2;
    const int g = lane >> 2, tig = lane & 3;
    const int row0 = blockIdx.y * 128;
    const int col0 = blockIdx.x * 128;

    float d[2][8][4];
#pragma unroll
    for (int mi = 0; mi < 2; mi++)
#pragma unroll
        for (int ni = 0; ni < 8; ni++)
#pragma unroll
            for (int q = 0; q < 4; q++) d[mi][ni][q] = 0.f;

    for (int kc = 0; kc < 4; kc++) {
        __syncthreads();
        // load + cvt + store: A and B chunks, 128x64 f32 each
#pragma unroll
        for (int it = 0; it < 8; it++) {
            int u = tid + it * 256;       // 0..2047 float4 units
            int r = u >> 4;
            int c4 = (u & 15) * 4;
            const float* ap;
            if (MODE == 0) {
                int arow = row0 + r;
                ap = (arow < NHALF) ? (A0 + (size_t)arow * DDIM)
                                    : (A1 + (size_t)(arow - NHALF) * DDIM);
            } else {
                ap = g_a + (size_t)(row0 + r) * DDIM;
            }
            float4 va = *(const float4*)(ap + kc * 64 + c4);
            uint32_t* dA = sA + r * PSTR + c4;
            dA[0] = f2tf32(va.x); dA[1] = f2tf32(va.y);
            dA[2] = f2tf32(va.z); dA[3] = f2tf32(va.w);
            float4 vb = *(const float4*)(B + (size_t)(col0 + r) * DDIM + kc * 64 + c4);
            uint32_t* dB = sB + r * PSTR + c4;
            dB[0] = f2tf32(vb.x); dB[1] = f2tf32(vb.y);
            dB[2] = f2tf32(vb.z); dB[3] = f2tf32(vb.w);
        }
        __syncthreads();

#pragma unroll
        for (int q = 0; q < 8; q++) {
            const int k0 = q * 8;
            uint32_t a[2][4];
#pragma unroll
            for (int mi = 0; mi < 2; mi++) {
                const uint32_t* base = sA + (wr * 32 + mi * 16 + g) * PSTR + k0 + tig;
                a[mi][0] = base[0];
                a[mi][1] = base[8 * PSTR];
                a[mi][2] = base[4];
                a[mi][3] = base[8 * PSTR + 4];
            }
#pragma unroll
            for (int ni = 0; ni < 8; ni++) {
                const uint32_t* bb = sB + (wc * 64 + ni * 8 + g) * PSTR + k0 + tig;
                uint32_t b0 = bb[0], b1 = bb[4];
#pragma unroll
                for (int mi = 0; mi < 2; mi++) mma_tf32(d[mi][ni], a[mi], b0, b1);
            }
        }
    }

    float* C = (MODE == 0) ? g_a : g_n;
#pragma unroll
    for (int mi = 0; mi < 2; mi++) {
        int gr = row0 + wr * 32 + mi * 16 + g;
#pragma unroll
        for (int ni = 0; ni < 8; ni++) {
            int gc = col0 + wc * 64 + ni * 8 + tig * 2;
            float bs0 = bias[gc], bs1 = bias[gc + 1];
            float v0 = d[mi][ni][0] + bs0;
            float v1 = d[mi][ni][1] + bs1;
            float v2 = d[mi][ni][2] + bs0;
            float v3 = d[mi][ni][3] + bs1;
            if (MODE == 0) {
                v0 = v0 > 0.f ? v0 : expm1f(v0);
                v1 = v1 > 0.f ? v1 : expm1f(v1);
                v2 = v2 > 0.f ? v2 : expm1f(v2);
                v3 = v3 > 0.f ? v3 : expm1f(v3);
            }
            C[(size_t)gr * DDIM + gc]           = v0;
            C[(size_t)gr * DDIM + gc + 1]       = v1;
            C[(size_t)(gr + 8) * DDIM + gc]     = v2;
            C[(size_t)(gr + 8) * DDIM + gc + 1] = v3;
        }
    }
}

// ---------------------------------------------------------------------------
// Fused: L2-normalize rows i and i+NHALF, exact fp32 s12, emit bf16.
// ---------------------------------------------------------------------------
__global__ void norm2_kernel() {
    int i = blockIdx.x;
    int t = threadIdx.x;
    float x1 = g_n[(size_t)i * DDIM + t];
    float x2 = g_n[(size_t)(i + NHALF) * DDIM + t];
    float s1 = x1 * x1, s2 = x2 * x2, dp = x1 * x2;
#pragma unroll
    for (int o = 16; o; o >>= 1) {
        s1 += __shfl_xor_sync(0xffffffffu, s1, o);
        s2 += __shfl_xor_sync(0xffffffffu, s2, o);
        dp += __shfl_xor_sync(0xffffffffu, dp, o);
    }
    __shared__ float ws[3][8];
    if ((t & 31) == 0) { ws[0][t >> 5] = s1; ws[1][t >> 5] = s2; ws[2][t >> 5] = dp; }
    __syncthreads();
    float t1 = 0.f, t2 = 0.f, td = 0.f;
#pragma unroll
    for (int w = 0; w < 8; w++) { t1 += ws[0][w]; t2 += ws[1][w]; td += ws[2][w]; }
    float inv1 = 1.f / fmaxf(sqrtf(t1), 1e-12f);
    float inv2 = 1.f / fmaxf(sqrtf(t2), 1e-12f);
    g_nb[(size_t)i * DDIM + t]           = __float2bfloat16(x1 * inv1);
    g_nb[(size_t)(i + NHALF) * DDIM + t] = __float2bfloat16(x2 * inv2);
    if (t == 0) g_s12[i] = td * inv1 * inv2;
}

// ---------------------------------------------------------------------------
// Gram + exp + reductions via bf16 mma.sync. 128x128x256 per CTA.
// cp.async K-chunk pipeline (4 chunks of 64, commit group per chunk).
// ---------------------------------------------------------------------------
__global__ void __launch_bounds__(256, 1)
sim_mma()
{
    extern __shared__ char smem[];

    const int t = blockIdx.x;
    int bi = (int)((257.0 - sqrt(66049.0 - 8.0 * (double)t)) * 0.5);
    if (bi < 0) bi = 0;
    if (bi > 127) bi = 127;
    while (bi > 0 && bi * (257 - bi) / 2 > t) bi--;
    while (bi < 127 && (bi + 1) * (257 - (bi + 1)) / 2 <= t) bi++;
    const int bj = bi + (t - bi * (257 - bi) / 2);

    const int tid = threadIdx.x;
    const int wid = tid >> 5, lane = tid & 31;
    const int wr = wid & 3, wc = wid >> 2;
    const int row0 = bi * 128, col0 = bj * 128;

    const uint32_t sA = smem_u32(smem);
    const uint32_t sB = (bi == bj) ? sA : (sA + TILE_BYTES);

    // issue all 4 K-chunk loads as cp.async, one commit group per chunk
    const char* srcA = (const char*)g_nb + (size_t)row0 * 512;
    const char* srcB = (const char*)g_nb + (size_t)col0 * 512;
#pragma unroll
    for (int c = 0; c < 4; c++) {
#pragma unroll
        for (int it = 0; it < 4; it++) {
            int u = tid + it * 256;       // 0..1023: 128 rows x 8 units
            int r = u >> 3;
            int cb = (u & 7) * 16;
            uint32_t dst = sA + r * STRB + c * 128 + cb;
            CP_ASYNC16(dst, srcA + (size_t)r * 512 + c * 128 + cb);
            if (bj != bi) {
                uint32_t dstb = sA + TILE_BYTES + r * STRB + c * 128 + cb;
                CP_ASYNC16(dstb, srcB + (size_t)r * 512 + c * 128 + cb);
            }
        }
        CP_COMMIT();
    }

    float d[2][8][4];
#pragma unroll
    for (int mi = 0; mi < 2; mi++)
#pragma unroll
        for (int ni = 0; ni < 8; ni++)
#pragma unroll
            for (int q = 0; q < 4; q++) d[mi][ni][q] = 0.f;

    const int lrow = lane & 15;
    const int lkof = (lane >> 4) * 16;

#pragma unroll
    for (int c = 0; c < 4; c++) {
        if (c == 0) CP_WAIT(3);
        else if (c == 1) CP_WAIT(2);
        else if (c == 2) CP_WAIT(1);
        else CP_WAIT(0);
        __syncthreads();
#pragma unroll
        for (int q = 0; q < 4; q++) {
            const int kb = (c * 4 + q) * 32;
            uint32_t a[2][4];
#pragma unroll
            for (int mi = 0; mi < 2; mi++) {
                uint32_t addr = sA + (wr * 32 + mi * 16 + lrow) * STRB + kb + lkof;
                ldsm4(a[mi][0], a[mi][1], a[mi][2], a[mi][3], addr);
            }
            uint32_t b0[8], b1[8];
#pragma unroll
            for (int nq = 0; nq < 4; nq++) {
                uint32_t addr = sB + (wc * 64 + nq * 16 + lrow) * STRB + kb + lkof;
                uint32_t q0, q1, q2, q3;
                ldsm4(q0, q1, q2, q3, addr);
                b0[nq * 2] = q0;     b1[nq * 2] = q2;
                b0[nq * 2 + 1] = q1; b1[nq * 2 + 1] = q3;
            }
#pragma unroll
            for (int mi = 0; mi < 2; mi++)
#pragma unroll
                for (int ni = 0; ni < 8; ni++)
                    mma16816(d[mi][ni], a[mi], b0[ni], b1[ni]);
        }
    }

    // ---- epilogue: exp, row sums, col sums ----
    const bool same = ((bi < 64) == (bj < 64));
    float* rs = same ? g_rs_same : g_rs_cross;

    float cp0[8], cp1[8];
#pragma unroll
    for (int ni = 0; ni < 8; ni++) { cp0[ni] = 0.f; cp1[ni] = 0.f; }

#pragma unroll
    for (int mi = 0; mi < 2; mi++) {
        float rp0 = 0.f, rp1 = 0.f;
#pragma unroll
        for (int ni = 0; ni < 8; ni++) {
            float e0 = __expf(2.f * d[mi][ni][0]);
            float e1 = __expf(2.f * d[mi][ni][1]);
            float e2 = __expf(2.f * d[mi][ni][2]);
            float e3 = __expf(2.f * d[mi][ni][3]);
            rp0 += e0 + e1;  rp1 += e2 + e3;
            cp0[ni] += e0 + e2;  cp1[ni] += e1 + e3;
        }
        rp0 += __shfl_xor_sync(0xffffffffu, rp0, 1);
        rp0 += __shfl_xor_sync(0xffffffffu, rp0, 2);
        rp1 += __shfl_xor_sync(0xffffffffu, rp1, 1);
        rp1 += __shfl_xor_sync(0xffffffffu, rp1, 2);
        if ((lane & 3) == 0) {
            int br = row0 + wr * 32 + mi * 16 + (lane >> 2);
            atomicAdd(&rs[br], rp0);
            atomicAdd(&rs[br + 8], rp1);
        }
    }

    if (bi != bj) {
#pragma unroll
        for (int ni = 0; ni < 8; ni++) {
            cp0[ni] += __shfl_xor_sync(0xffffffffu, cp0[ni], 4);
            cp0[ni] += __shfl_xor_sync(0xffffffffu, cp0[ni], 8);
            cp0[ni] += __shfl_xor_sync(0xffffffffu, cp0[ni], 16);
            cp1[ni] += __shfl_xor_sync(0xffffffffu, cp1[ni], 4);
            cp1[ni] += __shfl_xor_sync(0xffffffffu, cp1[ni], 8);
            cp1[ni] += __shfl_xor_sync(0xffffffffu, cp1[ni], 16);
        }
        if (lane < 4) {
#pragma unroll
            for (int ni = 0; ni < 8; ni++) {
                int bc = col0 + wc * 64 + ni * 8 + lane * 2;
                atomicAdd(&rs[bc], cp0[ni]);
                atomicAdd(&rs[bc + 1], cp1[ni]);
            }
        }
    }
}

__global__ void finalize_kernel(float* __restrict__ out) {
    int i = blockIdx.x * blockDim.x + threadIdx.x;
    if (i >= NHALF) return;
    const float E2 = 7.389056098930650f;   // exp(2) diagonal term (||n||=1)
    float den1 = g_rs_same[i] + g_rs_cross[i] - E2;
    float den2 = g_rs_same[i + NHALF] + g_rs_cross[i + NHALF] - E2;
    float twos = 2.0f * g_s12[i];
    out[i] = 0.5f * ((logf(den1) - twos) + (logf(den2) - twos));
}

extern "C" void kernel_launch(void* const* d_in, const int* in_sizes, int n_in,
                              void* d_out, int out_size) {
    const float* z1 = (const float*)d_in[0];
    const float* z2 = (const float*)d_in[1];
    const float* W1 = (const float*)d_in[2];
    const float* b1 = (const float*)d_in[3];
    const float* W2 = (const float*)d_in[4];
    const float* b2 = (const float*)d_in[5];
    float* out = (float*)d_out;

    cudaFuncSetAttribute(sim_mma, cudaFuncAttributeMaxDynamicSharedMemorySize,
                         SIM_SMEM);
    cudaFuncSetAttribute(proj_tc<0>, cudaFuncAttributeMaxDynamicSharedMemorySize,
                         PROJ_SMEM);
    cudaFuncSetAttribute(proj_tc<1>, cudaFuncAttributeMaxDynamicSharedMemorySize,
                         PROJ_SMEM);

    zero_kernel<<<(NTOT + 255) / 256, 256>>>();
    proj_tc<0><<<dim3(2, 128), 256, PROJ_SMEM>>>(z1, z2, W1, b1);
    proj_tc<1><<<dim3(2, 128), 256, PROJ_SMEM>>>(nullptr, nullptr, W2, b2);
    norm2_kernel<<<NHALF, 256>>>();
    sim_mma<<<NTILE_LIN, 256, SIM_SMEM>>>();
    finalize_kernel<<<NHALF / 256, 256>>>(out);
}

// round 9
// speedup vs baseline: 5.6483x; 1.3084x over previous
#include <cuda_runtime.h>
#include <cuda_bf16.h>
#include <math.h>
#include <stdint.h>

#define NHALF 8192
#define NTOT  16384
#define DDIM  256
#define NTILE_LIN 8256       // 129*128/2 upper-triangle tiles
#define PSTR  68             // proj: tf32 smem row stride in 4B words (64 + 4)
#define PROJ_SMEM (2 * 128 * PSTR * 4)

// sim: chunked double-buffered smem. Chunk = 128 rows x 64 bf16 cols.
#define CSTR   144                       // chunk row stride bytes (128 + 16)
#define CHUNK_BYTES (128 * CSTR)         // 18432
#define STAGE_BYTES (2 * CHUNK_BYTES)    // A + B = 36864
#define SIM_SMEM (2 * STAGE_BYTES)       // 2 stages = 73728

// ---- scratch ----
__device__ float g_a[(size_t)NTOT * DDIM];
__device__ float g_n[(size_t)NTOT * DDIM];
__device__ __nv_bfloat16 g_nb[(size_t)NTOT * DDIM];
__device__ float g_rs_same[NTOT];
__device__ float g_rs_cross[NTOT];
__device__ float g_s12[NHALF];

static __device__ __forceinline__ uint32_t smem_u32(const void* p) {
    uint32_t a;
    asm("{ .reg .u64 t; cvta.to.shared.u64 t, %1; cvt.u32.u64 %0, t; }"
        : "=r"(a) : "l"(p));
    return a;
}

static __device__ __forceinline__ void ldsm4(uint32_t& r0, uint32_t& r1,
                                             uint32_t& r2, uint32_t& r3,
                                             uint32_t addr) {
    asm volatile("ldmatrix.sync.aligned.m8n8.x4.shared.b16 {%0,%1,%2,%3}, [%4];"
                 : "=r"(r0), "=r"(r1), "=r"(r2), "=r"(r3) : "r"(addr));
}

static __device__ __forceinline__ void mma16816(float* d, const uint32_t* a,
                                                uint32_t b0, uint32_t b1) {
    asm volatile(
        "mma.sync.aligned.m16n8k16.row.col.f32.bf16.bf16.f32 "
        "{%0,%1,%2,%3}, {%4,%5,%6,%7}, {%8,%9}, {%0,%1,%2,%3};"
        : "+f"(d[0]), "+f"(d[1]), "+f"(d[2]), "+f"(d[3])
        : "r"(a[0]), "r"(a[1]), "r"(a[2]), "r"(a[3]), "r"(b0), "r"(b1));
}

static __device__ __forceinline__ void mma_tf32(float* d, const uint32_t* a,
                                                uint32_t b0, uint32_t b1) {
    asm volatile(
        "mma.sync.aligned.m16n8k8.row.col.f32.tf32.tf32.f32 "
        "{%0,%1,%2,%3}, {%4,%5,%6,%7}, {%8,%9}, {%0,%1,%2,%3};"
        : "+f"(d[0]), "+f"(d[1]), "+f"(d[2]), "+f"(d[3])
        : "r"(a[0]), "r"(a[1]), "r"(a[2]), "r"(a[3]), "r"(b0), "r"(b1));
}

static __device__ __forceinline__ uint32_t f2tf32(float x) {
    uint32_t u;
    asm("cvt.rna.tf32.f32 %0, %1;" : "=r"(u) : "f"(x));
    return u;
}

#define CP_ASYNC16(dst, src) \
    asm volatile("cp.async.cg.shared.global [%0], [%1], 16;" \
                 :: "r"(dst), "l"(src) : "memory")
#define CP_COMMIT() asm volatile("cp.async.commit_group;" ::: "memory")
#define CP_WAIT(n)  asm volatile("cp.async.wait_group %0;" :: "n"(n) : "memory")

__global__ void zero_kernel() {
    int i = blockIdx.x * blockDim.x + threadIdx.x;
    if (i < NTOT) { g_rs_same[i] = 0.f; g_rs_cross[i] = 0.f; }
}

// ---------------------------------------------------------------------------
// Projection GEMM via tf32 mma.sync (unchanged from R8).
// ---------------------------------------------------------------------------
template <int MODE>
__global__ void __launch_bounds__(256, 1)
proj_tc(const float* __restrict__ A0, const float* __restrict__ A1,
        const float* __restrict__ B,  const float* __restrict__ bias)
{
    extern __shared__ uint32_t psm[];
    uint32_t* sA = psm;
    uint32_t* sB = psm + 128 * PSTR;

    const int tid = threadIdx.x;
    const int wid = tid >> 5, lane = tid & 31;
    const int wr = wid & 3, wc = wid >> 2;
    const int g = lane >> 2, tig = lane & 3;
    const int row0 = blockIdx.y * 128;
    const int col0 = blockIdx.x * 128;

    float d[2][8][4];
#pragma unroll
    for (int mi = 0; mi < 2; mi++)
#pragma unroll
        for (int ni = 0; ni < 8; ni++)
#pragma unroll
            for (int q = 0; q < 4; q++) d[mi][ni][q] = 0.f;

    for (int kc = 0; kc < 4; kc++) {
        __syncthreads();
#pragma unroll
        for (int it = 0; it < 8; it++) {
            int u = tid + it * 256;
            int r = u >> 4;
            int c4 = (u & 15) * 4;
            const float* ap;
            if (MODE == 0) {
                int arow = row0 + r;
                ap = (arow < NHALF) ? (A0 + (size_t)arow * DDIM)
                                    : (A1 + (size_t)(arow - NHALF) * DDIM);
            } else {
                ap = g_a + (size_t)(row0 + r) * DDIM;
            }
            float4 va = *(const float4*)(ap + kc * 64 + c4);
            uint32_t* dA = sA + r * PSTR + c4;
            dA[0] = f2tf32(va.x); dA[1] = f2tf32(va.y);
            dA[2] = f2tf32(va.z); dA[3] = f2tf32(va.w);
            float4 vb = *(const float4*)(B + (size_t)(col0 + r) * DDIM + kc * 64 + c4);
            uint32_t* dB = sB + r * PSTR + c4;
            dB[0] = f2tf32(vb.x); dB[1] = f2tf32(vb.y);
            dB[2] = f2tf32(vb.z); dB[3] = f2tf32(vb.w);
        }
        __syncthreads();

#pragma unroll
        for (int q = 0; q < 8; q++) {
            const int k0 = q * 8;
            uint32_t a[2][4];
#pragma unroll
            for (int mi = 0; mi < 2; mi++) {
                const uint32_t* base = sA + (wr * 32 + mi * 16 + g) * PSTR + k0 + tig;
                a[mi][0] = base[0];
                a[mi][1] = base[8 * PSTR];
                a[mi][2] = base[4];
                a[mi][3] = base[8 * PSTR + 4];
            }
#pragma unroll
            for (int ni = 0; ni < 8; ni++) {
                const uint32_t* bb = sB + (wc * 64 + ni * 8 + g) * PSTR + k0 + tig;
                uint32_t b0 = bb[0], b1 = bb[4];
#pragma unroll
                for (int mi = 0; mi < 2; mi++) mma_tf32(d[mi][ni], a[mi], b0, b1);
            }
        }
    }

    float* C = (MODE == 0) ? g_a : g_n;
#pragma unroll
    for (int mi = 0; mi < 2; mi++) {
        int gr = row0 + wr * 32 + mi * 16 + g;
#pragma unroll
        for (int ni = 0; ni < 8; ni++) {
            int gc = col0 + wc * 64 + ni * 8 + tig * 2;
            float bs0 = bias[gc], bs1 = bias[gc + 1];
            float v0 = d[mi][ni][0] + bs0;
            float v1 = d[mi][ni][1] + bs1;
            float v2 = d[mi][ni][2] + bs0;
            float v3 = d[mi][ni][3] + bs1;
            if (MODE == 0) {
                v0 = v0 > 0.f ? v0 : expm1f(v0);
                v1 = v1 > 0.f ? v1 : expm1f(v1);
                v2 = v2 > 0.f ? v2 : expm1f(v2);
                v3 = v3 > 0.f ? v3 : expm1f(v3);
            }
            C[(size_t)gr * DDIM + gc]           = v0;
            C[(size_t)gr * DDIM + gc + 1]       = v1;
            C[(size_t)(gr + 8) * DDIM + gc]     = v2;
            C[(size_t)(gr + 8) * DDIM + gc + 1] = v3;
        }
    }
}

// ---------------------------------------------------------------------------
// Fused: L2-normalize rows i and i+NHALF, exact fp32 s12, emit bf16.
// ---------------------------------------------------------------------------
__global__ void norm2_kernel() {
    int i = blockIdx.x;
    int t = threadIdx.x;
    float x1 = g_n[(size_t)i * DDIM + t];
    float x2 = g_n[(size_t)(i + NHALF) * DDIM + t];
    float s1 = x1 * x1, s2 = x2 * x2, dp = x1 * x2;
#pragma unroll
    for (int o = 16; o; o >>= 1) {
        s1 += __shfl_xor_sync(0xffffffffu, s1, o);
        s2 += __shfl_xor_sync(0xffffffffu, s2, o);
        dp += __shfl_xor_sync(0xffffffffu, dp, o);
    }
    __shared__ float ws[3][8];
    if ((t & 31) == 0) { ws[0][t >> 5] = s1; ws[1][t >> 5] = s2; ws[2][t >> 5] = dp; }
    __syncthreads();
    float t1 = 0.f, t2 = 0.f, td = 0.f;
#pragma unroll
    for (int w = 0; w < 8; w++) { t1 += ws[0][w]; t2 += ws[1][w]; td += ws[2][w]; }
    float inv1 = 1.f / fmaxf(sqrtf(t1), 1e-12f);
    float inv2 = 1.f / fmaxf(sqrtf(t2), 1e-12f);
    g_nb[(size_t)i * DDIM + t]           = __float2bfloat16(x1 * inv1);
    g_nb[(size_t)(i + NHALF) * DDIM + t] = __float2bfloat16(x2 * inv2);
    if (t == 0) g_s12[i] = td * inv1 * inv2;
}

// ---------------------------------------------------------------------------
// Gram + exp + reductions via bf16 mma.sync. 128x128x256 per CTA.
// Chunked double-buffered cp.async smem (72KB) -> 2 CTAs/SM for overlap.
// ---------------------------------------------------------------------------
__global__ void __launch_bounds__(256, 2)
sim_mma()
{
    extern __shared__ char smem[];

    const int t = blockIdx.x;
    int bi = (int)((257.0 - sqrt(66049.0 - 8.0 * (double)t)) * 0.5);
    if (bi < 0) bi = 0;
    if (bi > 127) bi = 127;
    while (bi > 0 && bi * (257 - bi) / 2 > t) bi--;
    while (bi < 127 && (bi + 1) * (257 - (bi + 1)) / 2 <= t) bi++;
    const int bj = bi + (t - bi * (257 - bi) / 2);

    const int tid = threadIdx.x;
    const int wid = tid >> 5, lane = tid & 31;
    const int wr = wid & 3, wc = wid >> 2;
    const int row0 = bi * 128, col0 = bj * 128;

    const uint32_t s0 = smem_u32(smem);
    const char* srcA = (const char*)g_nb + (size_t)row0 * 512;
    const char* srcB = (const char*)g_nb + (size_t)col0 * 512;

    // issue chunk c into stage s: A at s*STAGE, B at s*STAGE + CHUNK
    const int lr = tid >> 3;            // 0..31 row base group (x4 iters)
    const int lcb = (tid & 7) * 16;     // byte within 128B chunk row

    auto issue_chunk = [&](int c, int s) {
        uint32_t dA = s0 + s * STAGE_BYTES;
        uint32_t dB = dA + CHUNK_BYTES;
        const char* sa = srcA + c * 128 + lcb;
        const char* sb = srcB + c * 128 + lcb;
#pragma unroll
        for (int it = 0; it < 4; it++) {
            int r = lr + it * 32;
            CP_ASYNC16(dA + r * CSTR + lcb, sa + (size_t)r * 512);
            CP_ASYNC16(dB + r * CSTR + lcb, sb + (size_t)r * 512);
        }
        CP_COMMIT();
    };

    issue_chunk(0, 0);
    issue_chunk(1, 1);

    float d[2][8][4];
#pragma unroll
    for (int mi = 0; mi < 2; mi++)
#pragma unroll
        for (int ni = 0; ni < 8; ni++)
#pragma unroll
            for (int q = 0; q < 4; q++) d[mi][ni][q] = 0.f;

    const int lrow = lane & 15;
    const int lkof = (lane >> 4) * 16;

#pragma unroll
    for (int c = 0; c < 4; c++) {
        CP_WAIT(1);
        __syncthreads();
        const uint32_t sA = s0 + (c & 1) * STAGE_BYTES;
        const uint32_t sB = sA + CHUNK_BYTES;
#pragma unroll
        for (int q = 0; q < 4; q++) {
            const int kb = q * 32;
            uint32_t a[2][4];
#pragma unroll
            for (int mi = 0; mi < 2; mi++) {
                uint32_t addr = sA + (wr * 32 + mi * 16 + lrow) * CSTR + kb + lkof;
                ldsm4(a[mi][0], a[mi][1], a[mi][2], a[mi][3], addr);
            }
            uint32_t b0[8], b1[8];
#pragma unroll
            for (int nq = 0; nq < 4; nq++) {
                uint32_t addr = sB + (wc * 64 + nq * 16 + lrow) * CSTR + kb + lkof;
                uint32_t q0, q1, q2, q3;
                ldsm4(q0, q1, q2, q3, addr);
                b0[nq * 2] = q0;     b1[nq * 2] = q2;
                b0[nq * 2 + 1] = q1; b1[nq * 2 + 1] = q3;
            }
#pragma unroll
            for (int mi = 0; mi < 2; mi++)
#pragma unroll
                for (int ni = 0; ni < 8; ni++)
                    mma16816(d[mi][ni], a[mi], b0[ni], b1[ni]);
        }
        __syncthreads();
        if (c < 2) issue_chunk(c + 2, c & 1);
    }

    // ---- epilogue: exp, row sums, col sums ----
    const bool same = ((bi < 64) == (bj < 64));
    float* rs = same ? g_rs_same : g_rs_cross;

    float cp0[8], cp1[8];
#pragma unroll
    for (int ni = 0; ni < 8; ni++) { cp0[ni] = 0.f; cp1[ni] = 0.f; }

#pragma unroll
    for (int mi = 0; mi < 2; mi++) {
        float rp0 = 0.f, rp1 = 0.f;
#pragma unroll
        for (int ni = 0; ni < 8; ni++) {
            float e0 = __expf(2.f * d[mi][ni][0]);
            float e1 = __expf(2.f * d[mi][ni][1]);
            float e2 = __expf(2.f * d[mi][ni][2]);
            float e3 = __expf(2.f * d[mi][ni][3]);
            rp0 += e0 + e1;  rp1 += e2 + e3;
            cp0[ni] += e0 + e2;  cp1[ni] += e1 + e3;
        }
        rp0 += __shfl_xor_sync(0xffffffffu, rp0, 1);
        rp0 += __shfl_xor_sync(0xffffffffu, rp0, 2);
        rp1 += __shfl_xor_sync(0xffffffffu, rp1, 1);
        rp1 += __shfl_xor_sync(0xffffffffu, rp1, 2);
        if ((lane & 3) == 0) {
            int br = row0 + wr * 32 + mi * 16 + (lane >> 2);
            atomicAdd(&rs[br], rp0);
            atomicAdd(&rs[br + 8], rp1);
        }
    }

    if (bi != bj) {
#pragma unroll
        for (int ni = 0; ni < 8; ni++) {
            cp0[ni] += __shfl_xor_sync(0xffffffffu, cp0[ni], 4);
            cp0[ni] += __shfl_xor_sync(0xffffffffu, cp0[ni], 8);
            cp0[ni] += __shfl_xor_sync(0xffffffffu, cp0[ni], 16);
            cp1[ni] += __shfl_xor_sync(0xffffffffu, cp1[ni], 4);
            cp1[ni] += __shfl_xor_sync(0xffffffffu, cp1[ni], 8);
            cp1[ni] += __shfl_xor_sync(0xffffffffu, cp1[ni], 16);
        }
        if (lane < 4) {
#pragma unroll
            for (int ni = 0; ni < 8; ni++) {
                int bc = col0 + wc * 64 + ni * 8 + lane * 2;
                atomicAdd(&rs[bc], cp0[ni]);
                atomicAdd(&rs[bc + 1], cp1[ni]);
            }
        }
    }
}

__global__ void finalize_kernel(float* __restrict__ out) {
    int i = blockIdx.x * blockDim.x + threadIdx.x;
    if (i >= NHALF) return;
    const float E2 = 7.389056098930650f;   // exp(2) diagonal term (||n||=1)
    float den1 = g_rs_same[i] + g_rs_cross[i] - E2;
    float den2 = g_rs_same[i + NHALF] + g_rs_cross[i + NHALF] - E2;
    float twos = 2.0f * g_s12[i];
    out[i] = 0.5f * ((logf(den1) - twos) + (logf(den2) - twos));
}

extern "C" void kernel_launch(void* const* d_in, const int* in_sizes, int n_in,
                              void* d_out, int out_size) {
    const float* z1 = (const float*)d_in[0];
    const float* z2 = (const float*)d_in[1];
    const float* W1 = (const float*)d_in[2];
    const float* b1 = (const float*)d_in[3];
    const float* W2 = (const float*)d_in[4];
    const float* b2 = (const float*)d_in[5];
    float* out = (float*)d_out;

    cudaFuncSetAttribute(sim_mma, cudaFuncAttributeMaxDynamicSharedMemorySize,
                         SIM_SMEM);
    cudaFuncSetAttribute(proj_tc<0>, cudaFuncAttributeMaxDynamicSharedMemorySize,
                         PROJ_SMEM);
    cudaFuncSetAttribute(proj_tc<1>, cudaFuncAttributeMaxDynamicSharedMemorySize,
                         PROJ_SMEM);

    zero_kernel<<<(NTOT + 255) / 256, 256>>>();
    proj_tc<0><<<dim3(2, 128), 256, PROJ_SMEM>>>(z1, z2, W1, b1);
    proj_tc<1><<<dim3(2, 128), 256, PROJ_SMEM>>>(nullptr, nullptr, W2, b2);
    norm2_kernel<<<NHALF, 256>>>();
    sim_mma<<<NTILE_LIN, 256, SIM_SMEM>>>();
    finalize_kernel<<<NHALF / 256, 256>>>(out);
}

// round 10
// speedup vs baseline: 5.9419x; 1.0520x over previous
#include <cuda_runtime.h>
#include <cuda_bf16.h>
#include <math.h>
#include <stdint.h>

#define NHALF 8192
#define NTOT  16384
#define DDIM  256
#define NTILE_LIN 8256       // 129*128/2 upper-triangle tiles
#define PSTR  68             // proj: tf32 smem row stride in 4B words (64 + 4)
#define PROJ_SMEM (2 * 128 * PSTR * 4)

// sim: chunked double-buffered smem. Chunk = 128 rows x 64 bf16 cols.
#define CSTR   144                       // chunk row stride bytes (128 + 16)
#define CHUNK_BYTES (128 * CSTR)         // 18432
#define STAGE_BYTES (2 * CHUNK_BYTES)    // A + B = 36864
#define SIM_SMEM (2 * STAGE_BYTES)       // 2 stages = 73728

// ---- scratch ----
__device__ float g_a[(size_t)NTOT * DDIM];
__device__ float g_n[(size_t)NTOT * DDIM];
__device__ __nv_bfloat16 g_nb[(size_t)NTOT * DDIM];
__device__ float g_rs_same[NTOT];
__device__ float g_rs_cross[NTOT];
__device__ float g_s12[NHALF];

static __device__ __forceinline__ uint32_t smem_u32(const void* p) {
    uint32_t a;
    asm("{ .reg .u64 t; cvta.to.shared.u64 t, %1; cvt.u32.u64 %0, t; }"
        : "=r"(a) : "l"(p));
    return a;
}

static __device__ __forceinline__ void ldsm4(uint32_t& r0, uint32_t& r1,
                                             uint32_t& r2, uint32_t& r3,
                                             uint32_t addr) {
    asm volatile("ldmatrix.sync.aligned.m8n8.x4.shared.b16 {%0,%1,%2,%3}, [%4];"
                 : "=r"(r0), "=r"(r1), "=r"(r2), "=r"(r3) : "r"(addr));
}

static __device__ __forceinline__ void mma16816(float* d, const uint32_t* a,
                                                uint32_t b0, uint32_t b1) {
    asm volatile(
        "mma.sync.aligned.m16n8k16.row.col.f32.bf16.bf16.f32 "
        "{%0,%1,%2,%3}, {%4,%5,%6,%7}, {%8,%9}, {%0,%1,%2,%3};"
        : "+f"(d[0]), "+f"(d[1]), "+f"(d[2]), "+f"(d[3])
        : "r"(a[0]), "r"(a[1]), "r"(a[2]), "r"(a[3]), "r"(b0), "r"(b1));
}

static __device__ __forceinline__ void mma_tf32(float* d, const uint32_t* a,
                                                uint32_t b0, uint32_t b1) {
    asm volatile(
        "mma.sync.aligned.m16n8k8.row.col.f32.tf32.tf32.f32 "
        "{%0,%1,%2,%3}, {%4,%5,%6,%7}, {%8,%9}, {%0,%1,%2,%3};"
        : "+f"(d[0]), "+f"(d[1]), "+f"(d[2]), "+f"(d[3])
        : "r"(a[0]), "r"(a[1]), "r"(a[2]), "r"(a[3]), "r"(b0), "r"(b1));
}

static __device__ __forceinline__ uint32_t f2tf32(float x) {
    uint32_t u;
    asm("cvt.rna.tf32.f32 %0, %1;" : "=r"(u) : "f"(x));
    return u;
}

#define CP_ASYNC16(dst, src) \
    asm volatile("cp.async.cg.shared.global [%0], [%1], 16;" \
                 :: "r"(dst), "l"(src) : "memory")
#define CP_COMMIT() asm volatile("cp.async.commit_group;" ::: "memory")
#define CP_WAIT(n)  asm volatile("cp.async.wait_group %0;" :: "n"(n) : "memory")

__global__ void zero_kernel() {
    int i = blockIdx.x * blockDim.x + threadIdx.x;
    if (i < NTOT) { g_rs_same[i] = 0.f; g_rs_cross[i] = 0.f; }
}

// ---------------------------------------------------------------------------
// Projection GEMM via tf32 mma.sync. Now 2 CTAs/SM to hide the serial
// load/convert phases behind the other CTA's MMA mainloop.
// ---------------------------------------------------------------------------
template <int MODE>
__global__ void __launch_bounds__(256, 2)
proj_tc(const float* __restrict__ A0, const float* __restrict__ A1,
        const float* __restrict__ B,  const float* __restrict__ bias)
{
    extern __shared__ uint32_t psm[];
    uint32_t* sA = psm;
    uint32_t* sB = psm + 128 * PSTR;

    const int tid = threadIdx.x;
    const int wid = tid >> 5, lane = tid & 31;
    const int wr = wid & 3, wc = wid >> 2;
    const int g = lane >> 2, tig = lane & 3;
    const int row0 = blockIdx.y * 128;
    const int col0 = blockIdx.x * 128;

    float d[2][8][4];
#pragma unroll
    for (int mi = 0; mi < 2; mi++)
#pragma unroll
        for (int ni = 0; ni < 8; ni++)
#pragma unroll
            for (int q = 0; q < 4; q++) d[mi][ni][q] = 0.f;

    for (int kc = 0; kc < 4; kc++) {
        __syncthreads();
#pragma unroll
        for (int it = 0; it < 8; it++) {
            int u = tid + it * 256;
            int r = u >> 4;
            int c4 = (u & 15) * 4;
            const float* ap;
            if (MODE == 0) {
                int arow = row0 + r;
                ap = (arow < NHALF) ? (A0 + (size_t)arow * DDIM)
                                    : (A1 + (size_t)(arow - NHALF) * DDIM);
            } else {
                ap = g_a + (size_t)(row0 + r) * DDIM;
            }
            float4 va = *(const float4*)(ap + kc * 64 + c4);
            uint32_t* dA = sA + r * PSTR + c4;
            dA[0] = f2tf32(va.x); dA[1] = f2tf32(va.y);
            dA[2] = f2tf32(va.z); dA[3] = f2tf32(va.w);
            float4 vb = *(const float4*)(B + (size_t)(col0 + r) * DDIM + kc * 64 + c4);
            uint32_t* dB = sB + r * PSTR + c4;
            dB[0] = f2tf32(vb.x); dB[1] = f2tf32(vb.y);
            dB[2] = f2tf32(vb.z); dB[3] = f2tf32(vb.w);
        }
        __syncthreads();

#pragma unroll
        for (int q = 0; q < 8; q++) {
            const int k0 = q * 8;
            uint32_t a[2][4];
#pragma unroll
            for (int mi = 0; mi < 2; mi++) {
                const uint32_t* base = sA + (wr * 32 + mi * 16 + g) * PSTR + k0 + tig;
                a[mi][0] = base[0];
                a[mi][1] = base[8 * PSTR];
                a[mi][2] = base[4];
                a[mi][3] = base[8 * PSTR + 4];
            }
#pragma unroll
            for (int ni = 0; ni < 8; ni++) {
                const uint32_t* bb = sB + (wc * 64 + ni * 8 + g) * PSTR + k0 + tig;
                uint32_t b0 = bb[0], b1 = bb[4];
#pragma unroll
                for (int mi = 0; mi < 2; mi++) mma_tf32(d[mi][ni], a[mi], b0, b1);
            }
        }
    }

    float* C = (MODE == 0) ? g_a : g_n;
#pragma unroll
    for (int mi = 0; mi < 2; mi++) {
        int gr = row0 + wr * 32 + mi * 16 + g;
#pragma unroll
        for (int ni = 0; ni < 8; ni++) {
            int gc = col0 + wc * 64 + ni * 8 + tig * 2;
            float bs0 = bias[gc], bs1 = bias[gc + 1];
            float v0 = d[mi][ni][0] + bs0;
            float v1 = d[mi][ni][1] + bs1;
            float v2 = d[mi][ni][2] + bs0;
            float v3 = d[mi][ni][3] + bs1;
            if (MODE == 0) {
                v0 = v0 > 0.f ? v0 : expm1f(v0);
                v1 = v1 > 0.f ? v1 : expm1f(v1);
                v2 = v2 > 0.f ? v2 : expm1f(v2);
                v3 = v3 > 0.f ? v3 : expm1f(v3);
            }
            C[(size_t)gr * DDIM + gc]           = v0;
            C[(size_t)gr * DDIM + gc + 1]       = v1;
            C[(size_t)(gr + 8) * DDIM + gc]     = v2;
            C[(size_t)(gr + 8) * DDIM + gc + 1] = v3;
        }
    }
}

// ---------------------------------------------------------------------------
// Fused: L2-normalize rows i and i+NHALF, exact fp32 s12, emit bf16.
// ---------------------------------------------------------------------------
__global__ void norm2_kernel() {
    int i = blockIdx.x;
    int t = threadIdx.x;
    float x1 = g_n[(size_t)i * DDIM + t];
    float x2 = g_n[(size_t)(i + NHALF) * DDIM + t];
    float s1 = x1 * x1, s2 = x2 * x2, dp = x1 * x2;
#pragma unroll
    for (int o = 16; o; o >>= 1) {
        s1 += __shfl_xor_sync(0xffffffffu, s1, o);
        s2 += __shfl_xor_sync(0xffffffffu, s2, o);
        dp += __shfl_xor_sync(0xffffffffu, dp, o);
    }
    __shared__ float ws[3][8];
    if ((t & 31) == 0) { ws[0][t >> 5] = s1; ws[1][t >> 5] = s2; ws[2][t >> 5] = dp; }
    __syncthreads();
    float t1 = 0.f, t2 = 0.f, td = 0.f;
#pragma unroll
    for (int w = 0; w < 8; w++) { t1 += ws[0][w]; t2 += ws[1][w]; td += ws[2][w]; }
    float inv1 = 1.f / fmaxf(sqrtf(t1), 1e-12f);
    float inv2 = 1.f / fmaxf(sqrtf(t2), 1e-12f);
    g_nb[(size_t)i * DDIM + t]           = __float2bfloat16(x1 * inv1);
    g_nb[(size_t)(i + NHALF) * DDIM + t] = __float2bfloat16(x2 * inv2);
    if (t == 0) g_s12[i] = td * inv1 * inv2;
}

// ---------------------------------------------------------------------------
// Gram + exp + reductions via bf16 mma.sync. 128x128x256 per CTA.
// Chunked double-buffered cp.async smem (72KB) -> 2 CTAs/SM.
// Column sums reduced through smem (128 atomics/tile instead of 512).
// ---------------------------------------------------------------------------
__global__ void __launch_bounds__(256, 2)
sim_mma()
{
    extern __shared__ char smem[];

    const int t = blockIdx.x;
    int bi = (int)((257.0 - sqrt(66049.0 - 8.0 * (double)t)) * 0.5);
    if (bi < 0) bi = 0;
    if (bi > 127) bi = 127;
    while (bi > 0 && bi * (257 - bi) / 2 > t) bi--;
    while (bi < 127 && (bi + 1) * (257 - (bi + 1)) / 2 <= t) bi++;
    const int bj = bi + (t - bi * (257 - bi) / 2);

    const int tid = threadIdx.x;
    const int wid = tid >> 5, lane = tid & 31;
    const int wr = wid & 3, wc = wid >> 2;
    const int row0 = bi * 128, col0 = bj * 128;

    const uint32_t s0 = smem_u32(smem);
    const char* srcA = (const char*)g_nb + (size_t)row0 * 512;
    const char* srcB = (const char*)g_nb + (size_t)col0 * 512;

    const int lr = tid >> 3;            // 0..31 row base group (x4 iters)
    const int lcb = (tid & 7) * 16;     // byte within 128B chunk row

    auto issue_chunk = [&](int c, int s) {
        uint32_t dA = s0 + s * STAGE_BYTES;
        uint32_t dB = dA + CHUNK_BYTES;
        const char* sa = srcA + c * 128 + lcb;
        const char* sb = srcB + c * 128 + lcb;
#pragma unroll
        for (int it = 0; it < 4; it++) {
            int r = lr + it * 32;
            CP_ASYNC16(dA + r * CSTR + lcb, sa + (size_t)r * 512);
            CP_ASYNC16(dB + r * CSTR + lcb, sb + (size_t)r * 512);
        }
        CP_COMMIT();
    };

    issue_chunk(0, 0);
    issue_chunk(1, 1);

    float d[2][8][4];
#pragma unroll
    for (int mi = 0; mi < 2; mi++)
#pragma unroll
        for (int ni = 0; ni < 8; ni++)
#pragma unroll
            for (int q = 0; q < 4; q++) d[mi][ni][q] = 0.f;

    const int lrow = lane & 15;
    const int lkof = (lane >> 4) * 16;

#pragma unroll
    for (int c = 0; c < 4; c++) {
        CP_WAIT(1);
        __syncthreads();
        const uint32_t sA = s0 + (c & 1) * STAGE_BYTES;
        const uint32_t sB = sA + CHUNK_BYTES;
#pragma unroll
        for (int q = 0; q < 4; q++) {
            const int kb = q * 32;
            uint32_t a[2][4];
#pragma unroll
            for (int mi = 0; mi < 2; mi++) {
                uint32_t addr = sA + (wr * 32 + mi * 16 + lrow) * CSTR + kb + lkof;
                ldsm4(a[mi][0], a[mi][1], a[mi][2], a[mi][3], addr);
            }
            uint32_t b0[8], b1[8];
#pragma unroll
            for (int nq = 0; nq < 4; nq++) {
                uint32_t addr = sB + (wc * 64 + nq * 16 + lrow) * CSTR + kb + lkof;
                uint32_t q0, q1, q2, q3;
                ldsm4(q0, q1, q2, q3, addr);
                b0[nq * 2] = q0;     b1[nq * 2] = q2;
                b0[nq * 2 + 1] = q1; b1[nq * 2 + 1] = q3;
            }
#pragma unroll
            for (int mi = 0; mi < 2; mi++)
#pragma unroll
                for (int ni = 0; ni < 8; ni++)
                    mma16816(d[mi][ni], a[mi], b0[ni], b1[ni]);
        }
        __syncthreads();
        if (c < 2) issue_chunk(c + 2, c & 1);
    }

    // ---- epilogue: exp, row sums, col sums ----
    const bool same = ((bi < 64) == (bj < 64));
    float* rs = same ? g_rs_same : g_rs_cross;

    float cp0[8], cp1[8];
#pragma unroll
    for (int ni = 0; ni < 8; ni++) { cp0[ni] = 0.f; cp1[ni] = 0.f; }

#pragma unroll
    for (int mi = 0; mi < 2; mi++) {
        float rp0 = 0.f, rp1 = 0.f;
#pragma unroll
        for (int ni = 0; ni < 8; ni++) {
            float e0 = __expf(2.f * d[mi][ni][0]);
            float e1 = __expf(2.f * d[mi][ni][1]);
            float e2 = __expf(2.f * d[mi][ni][2]);
            float e3 = __expf(2.f * d[mi][ni][3]);
            rp0 += e0 + e1;  rp1 += e2 + e3;
            cp0[ni] += e0 + e2;  cp1[ni] += e1 + e3;
        }
        rp0 += __shfl_xor_sync(0xffffffffu, rp0, 1);
        rp0 += __shfl_xor_sync(0xffffffffu, rp0, 2);
        rp1 += __shfl_xor_sync(0xffffffffu, rp1, 1);
        rp1 += __shfl_xor_sync(0xffffffffu, rp1, 2);
        if ((lane & 3) == 0) {
            int br = row0 + wr * 32 + mi * 16 + (lane >> 2);
            atomicAdd(&rs[br], rp0);
            atomicAdd(&rs[br + 8], rp1);
        }
    }

    if (bi != bj) {
        // reduce column partials across lanes (xor over row-provider groups)
#pragma unroll
        for (int ni = 0; ni < 8; ni++) {
            cp0[ni] += __shfl_xor_sync(0xffffffffu, cp0[ni], 4);
            cp0[ni] += __shfl_xor_sync(0xffffffffu, cp0[ni], 8);
            cp0[ni] += __shfl_xor_sync(0xffffffffu, cp0[ni], 16);
            cp1[ni] += __shfl_xor_sync(0xffffffffu, cp1[ni], 4);
            cp1[ni] += __shfl_xor_sync(0xffffffffu, cp1[ni], 8);
            cp1[ni] += __shfl_xor_sync(0xffffffffu, cp1[ni], 16);
        }
        // cross-warp reduce through smem: 4 warps share each wc column group.
        // red[wid][idx], idx = col within 64-wide group; 72-float row pad.
        float* red = (float*)smem;
        if (lane < 4) {
#pragma unroll
            for (int ni = 0; ni < 8; ni++) {
                red[wid * 72 + ni * 8 + lane * 2]     = cp0[ni];
                red[wid * 72 + ni * 8 + lane * 2 + 1] = cp1[ni];
            }
        }
        __syncthreads();
        if (tid < 128) {
            int cwc = tid >> 6;          // which 64-col group
            int idx = tid & 63;
            float s = red[(cwc * 4 + 0) * 72 + idx]
                    + red[(cwc * 4 + 1) * 72 + idx]
                    + red[(cwc * 4 + 2) * 72 + idx]
                    + red[(cwc * 4 + 3) * 72 + idx];
            atomicAdd(&rs[col0 + tid], s);
        }
    }
}

__global__ void finalize_kernel(float* __restrict__ out) {
    int i = blockIdx.x * blockDim.x + threadIdx.x;
    if (i >= NHALF) return;
    const float E2 = 7.389056098930650f;   // exp(2) diagonal term (||n||=1)
    float den1 = g_rs_same[i] + g_rs_cross[i] - E2;
    float den2 = g_rs_same[i + NHALF] + g_rs_cross[i + NHALF] - E2;
    float twos = 2.0f * g_s12[i];
    out[i] = 0.5f * ((logf(den1) - twos) + (logf(den2) - twos));
}

extern "C" void kernel_launch(void* const* d_in, const int* in_sizes, int n_in,
                              void* d_out, int out_size) {
    const float* z1 = (const float*)d_in[0];
    const float* z2 = (const float*)d_in[1];
    const float* W1 = (const float*)d_in[2];
    const float* b1 = (const float*)d_in[3];
    const float* W2 = (const float*)d_in[4];
    const float* b2 = (const float*)d_in[5];
    float* out = (float*)d_out;

    cudaFuncSetAttribute(sim_mma, cudaFuncAttributeMaxDynamicSharedMemorySize,
                         SIM_SMEM);
    cudaFuncSetAttribute(proj_tc<0>, cudaFuncAttributeMaxDynamicSharedMemorySize,
                         PROJ_SMEM);
    cudaFuncSetAttribute(proj_tc<1>, cudaFuncAttributeMaxDynamicSharedMemorySize,
                         PROJ_SMEM);

    zero_kernel<<<(NTOT + 255) / 256, 256>>>();
    proj_tc<0><<<dim3(2, 128), 256, PROJ_SMEM>>>(z1, z2, W1, b1);
    proj_tc<1><<<dim3(2, 128), 256, PROJ_SMEM>>>(nullptr, nullptr, W2, b2);
    norm2_kernel<<<NHALF, 256>>>();
    sim_mma<<<NTILE_LIN, 256, SIM_SMEM>>>();
    finalize_kernel<<<NHALF / 256, 256>>>(out);
}

// round 11
// speedup vs baseline: 6.3437x; 1.0676x over previous
#include <cuda_runtime.h>
#include <cuda_bf16.h>
#include <math.h>
#include <stdint.h>

#define NHALF 8192
#define NTOT  16384
#define DDIM  256
#define NTILE_LIN 8256       // 129*128/2 upper-triangle tiles
#define PSTR  68             // proj: tf32 smem row stride in 4B words (64 + 4)
#define PROJ_SMEM (2 * 128 * PSTR * 4)

// sim: chunked double-buffered smem. Chunk = 128 rows x 128 fp8 cols (128B).
#define CSTR   144                       // chunk row stride bytes (128 + 16)
#define CHUNK_BYTES (128 * CSTR)         // 18432
#define STAGE_BYTES (2 * CHUNK_BYTES)    // A + B = 36864
#define SIM_SMEM (2 * STAGE_BYTES)       // 2 stages = 73728

// ---- scratch ----
__device__ float g_a[(size_t)NTOT * DDIM];
__device__ float g_n[(size_t)NTOT * DDIM];
__device__ uint8_t g_n8[(size_t)NTOT * DDIM];   // e4m3 of n * 16
__device__ float g_rs_same[NTOT];
__device__ float g_rs_cross[NTOT];
__device__ float g_s12[NHALF];

static __device__ __forceinline__ uint32_t smem_u32(const void* p) {
    uint32_t a;
    asm("{ .reg .u64 t; cvta.to.shared.u64 t, %1; cvt.u32.u64 %0, t; }"
        : "=r"(a) : "l"(p));
    return a;
}

static __device__ __forceinline__ void ldsm4(uint32_t& r0, uint32_t& r1,
                                             uint32_t& r2, uint32_t& r3,
                                             uint32_t addr) {
    asm volatile("ldmatrix.sync.aligned.m8n8.x4.shared.b16 {%0,%1,%2,%3}, [%4];"
                 : "=r"(r0), "=r"(r1), "=r"(r2), "=r"(r3) : "r"(addr));
}

static __device__ __forceinline__ void mma_fp8(float* d, const uint32_t* a,
                                               uint32_t b0, uint32_t b1) {
    asm volatile(
        "mma.sync.aligned.m16n8k32.row.col.f32.e4m3.e4m3.f32 "
        "{%0,%1,%2,%3}, {%4,%5,%6,%7}, {%8,%9}, {%0,%1,%2,%3};"
        : "+f"(d[0]), "+f"(d[1]), "+f"(d[2]), "+f"(d[3])
        : "r"(a[0]), "r"(a[1]), "r"(a[2]), "r"(a[3]), "r"(b0), "r"(b1));
}

static __device__ __forceinline__ void mma_tf32(float* d, const uint32_t* a,
                                                uint32_t b0, uint32_t b1) {
    asm volatile(
        "mma.sync.aligned.m16n8k8.row.col.f32.tf32.tf32.f32 "
        "{%0,%1,%2,%3}, {%4,%5,%6,%7}, {%8,%9}, {%0,%1,%2,%3};"
        : "+f"(d[0]), "+f"(d[1]), "+f"(d[2]), "+f"(d[3])
        : "r"(a[0]), "r"(a[1]), "r"(a[2]), "r"(a[3]), "r"(b0), "r"(b1));
}

static __device__ __forceinline__ uint32_t f2tf32(float x) {
    uint32_t u;
    asm("cvt.rna.tf32.f32 %0, %1;" : "=r"(u) : "f"(x));
    return u;
}

// pack two floats into e4m3x2: low byte = lo, high byte = hi
static __device__ __forceinline__ uint16_t f2e4m3x2(float lo, float hi) {
    uint16_t u;
    asm("cvt.rn.satfinite.e4m3x2.f32 %0, %1, %2;" : "=h"(u) : "f"(hi), "f"(lo));
    return u;
}

#define CP_ASYNC16(dst, src) \
    asm volatile("cp.async.cg.shared.global [%0], [%1], 16;" \
                 :: "r"(dst), "l"(src) : "memory")
#define CP_COMMIT() asm volatile("cp.async.commit_group;" ::: "memory")
#define CP_WAIT(n)  asm volatile("cp.async.wait_group %0;" :: "n"(n) : "memory")

__global__ void zero_kernel() {
    int i = blockIdx.x * blockDim.x + threadIdx.x;
    if (i < NTOT) { g_rs_same[i] = 0.f; g_rs_cross[i] = 0.f; }
}

// ---------------------------------------------------------------------------
// Projection GEMM via tf32 mma.sync (unchanged from R10).
// ---------------------------------------------------------------------------
template <int MODE>
__global__ void __launch_bounds__(256, 2)
proj_tc(const float* __restrict__ A0, const float* __restrict__ A1,
        const float* __restrict__ B,  const float* __restrict__ bias)
{
    extern __shared__ uint32_t psm[];
    uint32_t* sA = psm;
    uint32_t* sB = psm + 128 * PSTR;

    const int tid = threadIdx.x;
    const int wid = tid >> 5, lane = tid & 31;
    const int wr = wid & 3, wc = wid >> 2;
    const int g = lane >> 2, tig = lane & 3;
    const int row0 = blockIdx.y * 128;
    const int col0 = blockIdx.x * 128;

    float d[2][8][4];
#pragma unroll
    for (int mi = 0; mi < 2; mi++)
#pragma unroll
        for (int ni = 0; ni < 8; ni++)
#pragma unroll
            for (int q = 0; q < 4; q++) d[mi][ni][q] = 0.f;

    for (int kc = 0; kc < 4; kc++) {
        __syncthreads();
#pragma unroll
        for (int it = 0; it < 8; it++) {
            int u = tid + it * 256;
            int r = u >> 4;
            int c4 = (u & 15) * 4;
            const float* ap;
            if (MODE == 0) {
                int arow = row0 + r;
                ap = (arow < NHALF) ? (A0 + (size_t)arow * DDIM)
                                    : (A1 + (size_t)(arow - NHALF) * DDIM);
            } else {
                ap = g_a + (size_t)(row0 + r) * DDIM;
            }
            float4 va = *(const float4*)(ap + kc * 64 + c4);
            uint32_t* dA = sA + r * PSTR + c4;
            dA[0] = f2tf32(va.x); dA[1] = f2tf32(va.y);
            dA[2] = f2tf32(va.z); dA[3] = f2tf32(va.w);
            float4 vb = *(const float4*)(B + (size_t)(col0 + r) * DDIM + kc * 64 + c4);
            uint32_t* dB = sB + r * PSTR + c4;
            dB[0] = f2tf32(vb.x); dB[1] = f2tf32(vb.y);
            dB[2] = f2tf32(vb.z); dB[3] = f2tf32(vb.w);
        }
        __syncthreads();

#pragma unroll
        for (int q = 0; q < 8; q++) {
            const int k0 = q * 8;
            uint32_t a[2][4];
#pragma unroll
            for (int mi = 0; mi < 2; mi++) {
                const uint32_t* base = sA + (wr * 32 + mi * 16 + g) * PSTR + k0 + tig;
                a[mi][0] = base[0];
                a[mi][1] = base[8 * PSTR];
                a[mi][2] = base[4];
                a[mi][3] = base[8 * PSTR + 4];
            }
#pragma unroll
            for (int ni = 0; ni < 8; ni++) {
                const uint32_t* bb = sB + (wc * 64 + ni * 8 + g) * PSTR + k0 + tig;
                uint32_t b0 = bb[0], b1 = bb[4];
#pragma unroll
                for (int mi = 0; mi < 2; mi++) mma_tf32(d[mi][ni], a[mi], b0, b1);
            }
        }
    }

    float* C = (MODE == 0) ? g_a : g_n;
#pragma unroll
    for (int mi = 0; mi < 2; mi++) {
        int gr = row0 + wr * 32 + mi * 16 + g;
#pragma unroll
        for (int ni = 0; ni < 8; ni++) {
            int gc = col0 + wc * 64 + ni * 8 + tig * 2;
            float bs0 = bias[gc], bs1 = bias[gc + 1];
            float v0 = d[mi][ni][0] + bs0;
            float v1 = d[mi][ni][1] + bs1;
            float v2 = d[mi][ni][2] + bs0;
            float v3 = d[mi][ni][3] + bs1;
            if (MODE == 0) {
                v0 = v0 > 0.f ? v0 : expm1f(v0);
                v1 = v1 > 0.f ? v1 : expm1f(v1);
                v2 = v2 > 0.f ? v2 : expm1f(v2);
                v3 = v3 > 0.f ? v3 : expm1f(v3);
            }
            C[(size_t)gr * DDIM + gc]           = v0;
            C[(size_t)gr * DDIM + gc + 1]       = v1;
            C[(size_t)(gr + 8) * DDIM + gc]     = v2;
            C[(size_t)(gr + 8) * DDIM + gc + 1] = v3;
        }
    }
}

// ---------------------------------------------------------------------------
// Fused: L2-normalize rows i and i+NHALF, exact fp32 s12, emit e4m3(n*16).
// ---------------------------------------------------------------------------
__global__ void norm2_kernel() {
    int i = blockIdx.x;
    int t = threadIdx.x;
    float x1 = g_n[(size_t)i * DDIM + t];
    float x2 = g_n[(size_t)(i + NHALF) * DDIM + t];
    float s1 = x1 * x1, s2 = x2 * x2, dp = x1 * x2;
#pragma unroll
    for (int o = 16; o; o >>= 1) {
        s1 += __shfl_xor_sync(0xffffffffu, s1, o);
        s2 += __shfl_xor_sync(0xffffffffu, s2, o);
        dp += __shfl_xor_sync(0xffffffffu, dp, o);
    }
    __shared__ float ws[3][8];
    if ((t & 31) == 0) { ws[0][t >> 5] = s1; ws[1][t >> 5] = s2; ws[2][t >> 5] = dp; }
    __syncthreads();
    float t1 = 0.f, t2 = 0.f, td = 0.f;
#pragma unroll
    for (int w = 0; w < 8; w++) { t1 += ws[0][w]; t2 += ws[1][w]; td += ws[2][w]; }
    float inv1 = 16.f / fmaxf(sqrtf(t1), 1e-12f);   // scale by 16 for e4m3
    float inv2 = 16.f / fmaxf(sqrtf(t2), 1e-12f);
    float v1 = x1 * inv1;
    float v2 = x2 * inv2;
    float n1 = __shfl_down_sync(0xffffffffu, v1, 1);
    float n2 = __shfl_down_sync(0xffffffffu, v2, 1);
    if ((t & 1) == 0) {
        *(uint16_t*)(g_n8 + (size_t)i * DDIM + t)           = f2e4m3x2(v1, n1);
        *(uint16_t*)(g_n8 + (size_t)(i + NHALF) * DDIM + t) = f2e4m3x2(v2, n2);
    }
    if (t == 0) g_s12[i] = td * inv1 * inv2 * 0.00390625f;  // /256 undo 16*16
}

// ---------------------------------------------------------------------------
// Gram + exp + reductions via e4m3 mma.sync m16n8k32. 128x128x256 per CTA.
// 2 chunks of 128B (K=128 fp8 each), double-buffered cp.async, 2 CTAs/SM.
// Accumulator = 256 * s  (operands scaled by 16); exp(2s) = exp(acc/128).
// ---------------------------------------------------------------------------
__global__ void __launch_bounds__(256, 2)
sim_mma()
{
    extern __shared__ char smem[];

    const int t = blockIdx.x;
    int bi = (int)((257.0 - sqrt(66049.0 - 8.0 * (double)t)) * 0.5);
    if (bi < 0) bi = 0;
    if (bi > 127) bi = 127;
    while (bi > 0 && bi * (257 - bi) / 2 > t) bi--;
    while (bi < 127 && (bi + 1) * (257 - (bi + 1)) / 2 <= t) bi++;
    const int bj = bi + (t - bi * (257 - bi) / 2);

    const int tid = threadIdx.x;
    const int wid = tid >> 5, lane = tid & 31;
    const int wr = wid & 3, wc = wid >> 2;
    const int row0 = bi * 128, col0 = bj * 128;

    const uint32_t s0 = smem_u32(smem);
    const char* srcA = (const char*)g_n8 + (size_t)row0 * DDIM;
    const char* srcB = (const char*)g_n8 + (size_t)col0 * DDIM;

    const int lr = tid >> 3;            // 0..31 row base group (x4 iters)
    const int lcb = (tid & 7) * 16;     // byte within 128B chunk row

    auto issue_chunk = [&](int c, int s) {
        uint32_t dA = s0 + s * STAGE_BYTES;
        uint32_t dB = dA + CHUNK_BYTES;
        const char* sa = srcA + c * 128 + lcb;
        const char* sb = srcB + c * 128 + lcb;
#pragma unroll
        for (int it = 0; it < 4; it++) {
            int r = lr + it * 32;
            CP_ASYNC16(dA + r * CSTR + lcb, sa + (size_t)r * DDIM);
            CP_ASYNC16(dB + r * CSTR + lcb, sb + (size_t)r * DDIM);
        }
        CP_COMMIT();
    };

    issue_chunk(0, 0);
    issue_chunk(1, 1);

    float d[2][8][4];
#pragma unroll
    for (int mi = 0; mi < 2; mi++)
#pragma unroll
        for (int ni = 0; ni < 8; ni++)
#pragma unroll
            for (int q = 0; q < 4; q++) d[mi][ni][q] = 0.f;

    const int lrow = lane & 15;
    const int lkof = (lane >> 4) * 16;

#pragma unroll
    for (int c = 0; c < 2; c++) {
        if (c == 0) CP_WAIT(1); else CP_WAIT(0);
        __syncthreads();
        const uint32_t sA = s0 + c * STAGE_BYTES;
        const uint32_t sB = sA + CHUNK_BYTES;
#pragma unroll
        for (int q = 0; q < 4; q++) {
            const int kb = q * 32;      // 32 bytes = k32 fp8 per mma step
            uint32_t a[2][4];
#pragma unroll
            for (int mi = 0; mi < 2; mi++) {
                uint32_t addr = sA + (wr * 32 + mi * 16 + lrow) * CSTR + kb + lkof;
                ldsm4(a[mi][0], a[mi][1], a[mi][2], a[mi][3], addr);
            }
            uint32_t b0[8], b1[8];
#pragma unroll
            for (int nq = 0; nq < 4; nq++) {
                uint32_t addr = sB + (wc * 64 + nq * 16 + lrow) * CSTR + kb + lkof;
                uint32_t q0, q1, q2, q3;
                ldsm4(q0, q1, q2, q3, addr);
                b0[nq * 2] = q0;     b1[nq * 2] = q2;
                b0[nq * 2 + 1] = q1; b1[nq * 2 + 1] = q3;
            }
#pragma unroll
            for (int mi = 0; mi < 2; mi++)
#pragma unroll
                for (int ni = 0; ni < 8; ni++)
                    mma_fp8(d[mi][ni], a[mi], b0[ni], b1[ni]);
        }
        __syncthreads();
    }

    // ---- epilogue: exp(acc/128), row sums, col sums ----
    const bool same = ((bi < 64) == (bj < 64));
    float* rs = same ? g_rs_same : g_rs_cross;
    const float ESC = 0.0078125f;   // 2/256: undo 16*16 operand scaling, *2 for 1/tau

    float cp0[8], cp1[8];
#pragma unroll
    for (int ni = 0; ni < 8; ni++) { cp0[ni] = 0.f; cp1[ni] = 0.f; }

#pragma unroll
    for (int mi = 0; mi < 2; mi++) {
        float rp0 = 0.f, rp1 = 0.f;
#pragma unroll
        for (int ni = 0; ni < 8; ni++) {
            float e0 = __expf(ESC * d[mi][ni][0]);
            float e1 = __expf(ESC * d[mi][ni][1]);
            float e2 = __expf(ESC * d[mi][ni][2]);
            float e3 = __expf(ESC * d[mi][ni][3]);
            rp0 += e0 + e1;  rp1 += e2 + e3;
            cp0[ni] += e0 + e2;  cp1[ni] += e1 + e3;
        }
        rp0 += __shfl_xor_sync(0xffffffffu, rp0, 1);
        rp0 += __shfl_xor_sync(0xffffffffu, rp0, 2);
        rp1 += __shfl_xor_sync(0xffffffffu, rp1, 1);
        rp1 += __shfl_xor_sync(0xffffffffu, rp1, 2);
        if ((lane & 3) == 0) {
            int br = row0 + wr * 32 + mi * 16 + (lane >> 2);
            atomicAdd(&rs[br], rp0);
            atomicAdd(&rs[br + 8], rp1);
        }
    }

    if (bi != bj) {
#pragma unroll
        for (int ni = 0; ni < 8; ni++) {
            cp0[ni] += __shfl_xor_sync(0xffffffffu, cp0[ni], 4);
            cp0[ni] += __shfl_xor_sync(0xffffffffu, cp0[ni], 8);
            cp0[ni] += __shfl_xor_sync(0xffffffffu, cp0[ni], 16);
            cp1[ni] += __shfl_xor_sync(0xffffffffu, cp1[ni], 4);
            cp1[ni] += __shfl_xor_sync(0xffffffffu, cp1[ni], 8);
            cp1[ni] += __shfl_xor_sync(0xffffffffu, cp1[ni], 16);
        }
        float* red = (float*)smem;
        if (lane < 4) {
#pragma unroll
            for (int ni = 0; ni < 8; ni++) {
                red[wid * 72 + ni * 8 + lane * 2]     = cp0[ni];
                red[wid * 72 + ni * 8 + lane * 2 + 1] = cp1[ni];
            }
        }
        __syncthreads();
        if (tid < 128) {
            int cwc = tid >> 6;
            int idx = tid & 63;
            float s = red[(cwc * 4 + 0) * 72 + idx]
                    + red[(cwc * 4 + 1) * 72 + idx]
                    + red[(cwc * 4 + 2) * 72 + idx]
                    + red[(cwc * 4 + 3) * 72 + idx];
            atomicAdd(&rs[col0 + tid], s);
        }
    }
}

__global__ void finalize_kernel(float* __restrict__ out) {
    int i = blockIdx.x * blockDim.x + threadIdx.x;
    if (i >= NHALF) return;
    const float E2 = 7.389056098930650f;   // exp(2) diagonal term (||n||=1)
    float den1 = g_rs_same[i] + g_rs_cross[i] - E2;
    float den2 = g_rs_same[i + NHALF] + g_rs_cross[i + NHALF] - E2;
    float twos = 2.0f * g_s12[i];
    out[i] = 0.5f * ((logf(den1) - twos) + (logf(den2) - twos));
}

extern "C" void kernel_launch(void* const* d_in, const int* in_sizes, int n_in,
                              void* d_out, int out_size) {
    const float* z1 = (const float*)d_in[0];
    const float* z2 = (const float*)d_in[1];
    const float* W1 = (const float*)d_in[2];
    const float* b1 = (const float*)d_in[3];
    const float* W2 = (const float*)d_in[4];
    const float* b2 = (const float*)d_in[5];
    float* out = (float*)d_out;

    cudaFuncSetAttribute(sim_mma, cudaFuncAttributeMaxDynamicSharedMemorySize,
                         SIM_SMEM);
    cudaFuncSetAttribute(proj_tc<0>, cudaFuncAttributeMaxDynamicSharedMemorySize,
                         PROJ_SMEM);
    cudaFuncSetAttribute(proj_tc<1>, cudaFuncAttributeMaxDynamicSharedMemorySize,
                         PROJ_SMEM);

    zero_kernel<<<(NTOT + 255) / 256, 256>>>();
    proj_tc<0><<<dim3(2, 128), 256, PROJ_SMEM>>>(z1, z2, W1, b1);
    proj_tc<1><<<dim3(2, 128), 256, PROJ_SMEM>>>(nullptr, nullptr, W2, b2);
    norm2_kernel<<<NHALF, 256>>>();
    sim_mma<<<NTILE_LIN, 256, SIM_SMEM>>>();
    finalize_kernel<<<NHALF / 256, 256>>>(out);
}